// round 8
// baseline (speedup 1.0000x reference)
#include <cuda_runtime.h>
#include <cuda_bf16.h>
#include <cstdint>

#define N_PTS 16384
#define DIM   512
#define OUT_D 512
#define KNN   10
#define NCAND 16

// fp32 xw tiling
#define BM 128
#define BN 128
#define KCH 32
#define TPB 256
#define LDS_ 132

#define INF_F __int_as_float(0x7f800000)

__device__ float g_sq[N_PTS];
__device__ float g_xW[N_PTS * OUT_D];
__device__ __nv_bfloat16 g_hi[(size_t)N_PTS * DIM];
__device__ int g_cand[N_PTS * NCAND];

// ---------------- helpers ----------------
__device__ __forceinline__ uint32_t smem_u32(const void *p) {
    uint32_t a;
    asm("{ .reg .u64 t; cvta.to.shared.u64 t, %1; cvt.u32.u64 %0, t; }" : "=r"(a) : "l"(p));
    return a;
}
#define SW128(o) ((o) ^ (((o) >> 3) & 0x70))

__device__ __forceinline__ void cp_async16(uint32_t dst, const void *src) {
    asm volatile("cp.async.cg.shared.global [%0], [%1], 16;" :: "r"(dst), "l"(src) : "memory");
}
#define CP_COMMIT() asm volatile("cp.async.commit_group;" ::: "memory")
#define CP_WAIT(n)  asm volatile("cp.async.wait_group %0;" :: "n"(n) : "memory")

__device__ __forceinline__ void ldsm4(uint32_t &r0, uint32_t &r1, uint32_t &r2, uint32_t &r3,
                                      uint32_t addr) {
    asm volatile("ldmatrix.sync.aligned.m8n8.x4.shared.b16 {%0,%1,%2,%3}, [%4];"
                 : "=r"(r0), "=r"(r1), "=r"(r2), "=r"(r3) : "r"(addr));
}
__device__ __forceinline__ void mma_bf16(float &c0, float &c1, float &c2, float &c3,
                                         uint32_t a0, uint32_t a1, uint32_t a2, uint32_t a3,
                                         uint32_t b0, uint32_t b1) {
    asm volatile("mma.sync.aligned.m16n8k16.row.col.f32.bf16.bf16.f32 "
                 "{%0,%1,%2,%3}, {%4,%5,%6,%7}, {%8,%9}, {%0,%1,%2,%3};"
                 : "+f"(c0), "+f"(c1), "+f"(c2), "+f"(c3)
                 : "r"(a0), "r"(a1), "r"(a2), "r"(a3), "r"(b0), "r"(b1));
}

// ---------------- split: x -> bf16 hi ----------------
__global__ void __launch_bounds__(256) split_kernel(const float *__restrict__ x) {
    int t = blockIdx.x * 256 + threadIdx.x;
    float4 v = *(const float4 *)(x + (size_t)t * 4);
    __nv_bfloat162 p0, p1;
    p0.x = __float2bfloat16_rn(v.x); p0.y = __float2bfloat16_rn(v.y);
    p1.x = __float2bfloat16_rn(v.z); p1.y = __float2bfloat16_rn(v.w);
    __nv_bfloat16 *o = g_hi + (size_t)t * 4;
    *(__nv_bfloat162 *)(o) = p0;
    *(__nv_bfloat162 *)(o + 2) = p1;
}

// ---------------- row squared norms ----------------
__global__ void sq_kernel(const float *__restrict__ x) {
    int row = blockIdx.x * 8 + (threadIdx.x >> 5);
    int lane = threadIdx.x & 31;
    const float4 *xr = (const float4 *)(x + (long)row * DIM);
    float s = 0.f;
#pragma unroll
    for (int i = 0; i < 4; i++) {
        float4 v = xr[lane + i * 32];
        s += v.x * v.x + v.y * v.y + v.z * v.z + v.w * v.w;
    }
#pragma unroll
    for (int o = 16; o; o >>= 1) s += __shfl_xor_sync(0xFFFFFFFFu, s, o);
    if (lane == 0) g_sq[row] = s;
}

// ---------------- fp32 xW = x @ A ----------------
__device__ __forceinline__ unsigned long long pack2(float x, float y) {
    unsigned long long r; asm("mov.b64 %0, {%1, %2};" : "=l"(r) : "f"(x), "f"(y)); return r;
}
__device__ __forceinline__ void unpack2(unsigned long long v, float &a, float &b) {
    asm("mov.b64 {%0, %1}, %2;" : "=f"(a), "=f"(b) : "l"(v));
}
__device__ __forceinline__ void fma2(unsigned long long &d, unsigned long long a, unsigned long long b) {
    asm("fma.rn.f32x2 %0, %1, %2, %0;" : "+l"(d) : "l"(a), "l"(b));
}
__device__ __forceinline__ void load_T(float *dst, const float *__restrict__ src, int row0, int kc, int ld) {
    int t = threadIdx.x;
#pragma unroll
    for (int i = 0; i < 4; i++) {
        int idx = t + i * TPB, r = idx >> 3, f4 = idx & 7;
        float4 v = *(const float4 *)(src + (long)(row0 + r) * ld + kc + f4 * 4);
        dst[(f4 * 4 + 0) * LDS_ + r] = v.x; dst[(f4 * 4 + 1) * LDS_ + r] = v.y;
        dst[(f4 * 4 + 2) * LDS_ + r] = v.z; dst[(f4 * 4 + 3) * LDS_ + r] = v.w;
    }
}
__device__ __forceinline__ void load_N(float *dst, const float *__restrict__ src, int kc, int col0, int ld) {
    int t = threadIdx.x;
#pragma unroll
    for (int i = 0; i < 4; i++) {
        int idx = t + i * TPB, kk = idx >> 5, c4 = idx & 31;
        float4 v = *(const float4 *)(src + (long)(kc + kk) * ld + col0 + c4 * 4);
        *(float4 *)(dst + kk * LDS_ + c4 * 4) = v;
    }
}
__global__ void __launch_bounds__(TPB) xw_kernel(const float *__restrict__ x, const float *__restrict__ A) {
    __shared__ float Xs[KCH * LDS_], Ws[KCH * LDS_];
    int m0 = blockIdx.x * BM, n0 = blockIdx.y * BN;
    int w = threadIdx.x >> 5, l = threadIdx.x & 31;
    int tx = (l & 7) | ((w & 1) << 3), ty = (l >> 3) | ((w >> 1) << 2);
    unsigned long long acc[8][4];
#pragma unroll
    for (int i = 0; i < 8; i++)
#pragma unroll
        for (int j = 0; j < 4; j++) acc[i][j] = 0ull;
    for (int kc = 0; kc < DIM; kc += KCH) {
        __syncthreads();
        load_T(Xs, x, m0, kc, DIM);
        load_N(Ws, A, kc, n0, OUT_D);
        __syncthreads();
#pragma unroll 8
        for (int kk = 0; kk < KCH; kk++) {
            const float *ar = Xs + kk * LDS_ + ty * 8;
            const float *br = Ws + kk * LDS_ + tx * 8;
            unsigned long long b2[4], a2[8];
#pragma unroll
            for (int j = 0; j < 4; j++) b2[j] = *(const unsigned long long *)(br + j * 2);
#pragma unroll
            for (int i = 0; i < 8; i++) { float av = ar[i]; a2[i] = pack2(av, av); }
#pragma unroll
            for (int i = 0; i < 8; i++)
#pragma unroll
                for (int j = 0; j < 4; j++) fma2(acc[i][j], a2[i], b2[j]);
        }
    }
#pragma unroll
    for (int i = 0; i < 8; i++) {
        int m = m0 + ty * 8 + i;
#pragma unroll
        for (int j = 0; j < 4; j++) {
            float v0, v1; unpack2(acc[i][j], v0, v1);
            int n = n0 + tx * 8 + j * 2;
            g_xW[(long)m * OUT_D + n] = v0;
            g_xW[(long)m * OUT_D + n + 1] = v1;
        }
    }
}

// ---------------- HMMA bf16 distance sweep + approx top-16 ----------------
// R5 shape: 256 threads, warp grid 2(M)x4(N), warp tile 64x32, A tile resident.
// B streamed in 32KB chunks (two 64-col k-blocks per stage, 2 stages) -> 4 syncs/tile.
// smem: A 128KB | B 2x32KB | Ds 128x68 f32 (34816) | sqj 512
#define SM_A   0
#define SM_B   131072
#define SM_DS  196608
#define SM_SQJ 231424
#define SMEM_KNN 231936
#define DS_STRIDE 68

__global__ void __launch_bounds__(256, 1) knn_hmma_kernel() {
    extern __shared__ char sm[];
    uint32_t sb = smem_u32(sm);
    float *Ds = (float *)(sm + SM_DS);
    float *sqj_s = (float *)(sm + SM_SQJ);

    int tid = threadIdx.x;
    int lane = tid & 31, w = tid >> 5;
    int wm = w >> 2, wn = w & 3;          // warp grid 2(M) x 4(N)
    int hme = wn >> 1;                    // which 64-col half this warp outputs
    int r0 = blockIdx.x * 128;

    int lrow = lane & 15;
    int lkp  = (lane >> 4) * 8;

    // ---- preload full A tile (8 k-blocks) + B chunk 0 (j=0, k-cols 0..127) ----
    {
        const __nv_bfloat16 *Ab = g_hi + (size_t)r0 * DIM;
#pragma unroll
        for (int u = 0; u < 32; u++) {
            int g = tid + u * 256;
            int kblk = g >> 10, rem = g & 1023;
            int row = rem >> 3, k8 = (rem & 7) * 8;
            uint32_t dst = sb + SM_A + kblk * 16384 + SW128(row * 128 + k8 * 2);
            cp_async16(dst, Ab + (size_t)row * DIM + kblk * 64 + k8);
        }
        CP_COMMIT();
#pragma unroll
        for (int u = 0; u < 8; u++) {
            int g = tid + u * 256;                  // 0..2047
            int kb2 = g >> 10, rem = g & 1023;
            int row = rem >> 3, k8 = (rem & 7) * 8;
            uint32_t dst = sb + SM_B + kb2 * 16384 + SW128(row * 128 + k8 * 2);
            cp_async16(dst, g_hi + (size_t)row * DIM + kb2 * 64 + k8);
        }
        CP_COMMIT();
    }

    float bd[NCAND];
    int bi[NCAND];
#pragma unroll
    for (int k = 0; k < NCAND; k++) { bd[k] = INF_F; bi[k] = -1; }
    float th = INF_F;

    for (int j = 0; j < 128; j++) {
        float acc[4][4][4];
#pragma unroll
        for (int a = 0; a < 4; a++)
#pragma unroll
            for (int b = 0; b < 4; b++)
#pragma unroll
                for (int c = 0; c < 4; c++) acc[a][b][c] = 0.f;

        for (int c = 0; c < 4; c++) {              // 4 chunks of 128 k-cols
            int q = j * 4 + c;
            int stage = q & 1;

            CP_WAIT(0);
            __syncthreads();
            if (c == 0 && tid < 128) sqj_s[tid] = g_sq[j * 128 + tid];

            if (q + 1 < 512) {
                int qn = q + 1;
                int jn = qn >> 2, cn = qn & 3, sn = qn & 1;
#pragma unroll
                for (int u = 0; u < 8; u++) {
                    int g = tid + u * 256;
                    int kb2 = g >> 10, rem = g & 1023;
                    int row = rem >> 3, k8 = (rem & 7) * 8;
                    uint32_t dst = sb + SM_B + sn * 32768 + kb2 * 16384 +
                                   SW128(row * 128 + k8 * 2);
                    cp_async16(dst, g_hi + (size_t)(jn * 128 + row) * DIM +
                                         cn * 128 + kb2 * 64 + k8);
                }
                CP_COMMIT();
            }

#pragma unroll
            for (int kb2 = 0; kb2 < 2; kb2++) {
                uint32_t Ab = sb + SM_A + (c * 2 + kb2) * 16384;
                uint32_t Bb = sb + SM_B + stage * 32768 + kb2 * 16384;
#pragma unroll
                for (int ks = 0; ks < 4; ks++) {
                    int koff = ks * 16 + lkp;
                    uint32_t b0, b1, b2, b3, b4, b5, b6, b7;
                    {
                        int n = wn * 32 + lrow;
                        ldsm4(b0, b1, b2, b3, Bb + SW128(n * 128 + koff * 2));
                        ldsm4(b4, b5, b6, b7, Bb + SW128((n + 16) * 128 + koff * 2));
                    }
#pragma unroll
                    for (int mb = 0; mb < 4; mb++) {
                        uint32_t a0, a1, a2, a3;
                        int m = wm * 64 + mb * 16 + lrow;
                        ldsm4(a0, a1, a2, a3, Ab + SW128(m * 128 + koff * 2));
                        mma_bf16(acc[mb][0][0], acc[mb][0][1], acc[mb][0][2], acc[mb][0][3],
                                 a0, a1, a2, a3, b0, b2);
                        mma_bf16(acc[mb][1][0], acc[mb][1][1], acc[mb][1][2], acc[mb][1][3],
                                 a0, a1, a2, a3, b1, b3);
                        mma_bf16(acc[mb][2][0], acc[mb][2][1], acc[mb][2][2], acc[mb][2][3],
                                 a0, a1, a2, a3, b4, b6);
                        mma_bf16(acc[mb][3][0], acc[mb][3][1], acc[mb][3][2], acc[mb][3][3],
                                 a0, a1, a2, a3, b5, b7);
                    }
                }
            }
        }

        // ---- epilogue: two 64-col halves through Ds ----
#pragma unroll
        for (int half = 0; half < 2; half++) {
            __syncthreads();
            if (hme == half) {
#pragma unroll
                for (int mb = 0; mb < 4; mb++) {
                    int r1 = wm * 64 + mb * 16 + (lane >> 2);
#pragma unroll
                    for (int nb = 0; nb < 4; nb++) {
                        int cb = (wn & 1) * 32 + nb * 8 + (lane & 3) * 2;
                        float2 v0, v1;
                        v0.x = acc[mb][nb][0]; v0.y = acc[mb][nb][1];
                        v1.x = acc[mb][nb][2]; v1.y = acc[mb][nb][3];
                        *(float2 *)(Ds + r1 * DS_STRIDE + cb) = v0;
                        *(float2 *)(Ds + (r1 + 8) * DS_STRIDE + cb) = v1;
                    }
                }
            }
            __syncthreads();
            {
                int row = tid & 127, seg = tid >> 7;
                int gm = r0 + row;
                const float *dr = Ds + row * DS_STRIDE + seg * 32;
                int ctile = half * 64 + seg * 32;
                int jb = j * 128 + ctile;
#pragma unroll 4
                for (int c4 = 0; c4 < 8; c4++) {
                    float4 v = *(const float4 *)(dr + c4 * 4);
                    const float *sq4 = sqj_s + ctile + c4 * 4;
                    int cb = jb + c4 * 4;
                    float s0 = sq4[0] - 2.0f * v.x;
                    float s1 = sq4[1] - 2.0f * v.y;
                    float s2 = sq4[2] - 2.0f * v.z;
                    float s3 = sq4[3] - 2.0f * v.w;
                    if (s0 < th && cb + 0 != gm) {
                        int p = NCAND - 1;
                        while (p > 0 && bd[p - 1] > s0) { bd[p] = bd[p - 1]; bi[p] = bi[p - 1]; p--; }
                        bd[p] = s0; bi[p] = cb + 0; th = bd[NCAND - 1];
                    }
                    if (s1 < th && cb + 1 != gm) {
                        int p = NCAND - 1;
                        while (p > 0 && bd[p - 1] > s1) { bd[p] = bd[p - 1]; bi[p] = bi[p - 1]; p--; }
                        bd[p] = s1; bi[p] = cb + 1; th = bd[NCAND - 1];
                    }
                    if (s2 < th && cb + 2 != gm) {
                        int p = NCAND - 1;
                        while (p > 0 && bd[p - 1] > s2) { bd[p] = bd[p - 1]; bi[p] = bi[p - 1]; p--; }
                        bd[p] = s2; bi[p] = cb + 2; th = bd[NCAND - 1];
                    }
                    if (s3 < th && cb + 3 != gm) {
                        int p = NCAND - 1;
                        while (p > 0 && bd[p - 1] > s3) { bd[p] = bd[p - 1]; bi[p] = bi[p - 1]; p--; }
                        bd[p] = s3; bi[p] = cb + 3; th = bd[NCAND - 1];
                    }
                }
            }
        }
    }

    // ---- merge the two per-row half-lists (both sorted), emit top-16 ----
    __syncthreads();
    float *md = Ds;
    int *mi = (int *)(Ds + 4096);
#pragma unroll
    for (int k = 0; k < NCAND; k++) {
        md[tid * NCAND + k] = bd[k];
        mi[tid * NCAND + k] = bi[k];
    }
    __syncthreads();
    if (tid < 128) {
        const float *da = md + tid * NCAND;
        const int *ia = mi + tid * NCAND;
        const float *db = md + (tid + 128) * NCAND;
        const int *ib = mi + (tid + 128) * NCAND;
        int pa = 0, pb = 0;
#pragma unroll
        for (int k = 0; k < NCAND; k++) {
            float va = da[pa], vb = db[pb];
            bool takeA = (va < vb) || (va == vb && ia[pa] < ib[pb]);
            int sel = takeA ? ia[pa] : ib[pb];
            if (takeA) pa++; else pb++;
            g_cand[(r0 + tid) * NCAND + k] = sel;
        }
    }
}

// ---------------- exact fp32 rescore + gather-sum ----------------
__global__ void __launch_bounds__(512) rescore_kernel(const float *__restrict__ x,
                                                      float *__restrict__ out) {
    __shared__ float xr[512];
    __shared__ float cd[NCAND];
    __shared__ int ci[NCAND];
    __shared__ int sel[KNN];
    int row = blockIdx.x;
    int tid = threadIdx.x;
    int w = tid >> 5, lane = tid & 31;
    xr[tid] = x[(long)row * DIM + tid];
    if (tid < NCAND) ci[tid] = g_cand[row * NCAND + tid];
    __syncthreads();
    {
        int c = ci[w];
        float s = 0.f;
        if (c >= 0) {
            const float *xc = x + (long)c * DIM;
#pragma unroll
            for (int t = 0; t < 16; t++) {
                int e = lane + 32 * t;
                s += xr[e] * xc[e];
            }
        }
#pragma unroll
        for (int o = 16; o; o >>= 1) s += __shfl_xor_sync(0xFFFFFFFFu, s, o);
        if (lane == 0) cd[w] = (c >= 0) ? (g_sq[row] + g_sq[c] - 2.0f * s) : INF_F;
    }
    __syncthreads();
    if (tid == 0) {
        unsigned used = 0;
        for (int k = 0; k < KNN; k++) {
            float best = INF_F; int bidx = 0x7FFFFFFF, bw = 0;
            for (int q = 0; q < NCAND; q++) {
                if (used & (1u << q)) continue;
                float d = cd[q]; int id = ci[q];
                if (d < best || (d == best && id < bidx)) { best = d; bidx = id; bw = q; }
            }
            used |= 1u << bw;
            sel[k] = bidx;
        }
    }
    __syncthreads();
    float s = 0.f;
#pragma unroll
    for (int k = 0; k < KNN; k++) s += g_xW[(long)sel[k] * OUT_D + tid];
    out[(long)row * OUT_D + tid] = s;
}

// ---------------- launcher ----------------
extern "C" void kernel_launch(void *const *d_in, const int *in_sizes, int n_in,
                              void *d_out, int out_size) {
    const float *x = (const float *)d_in[0];
    const float *A = (const float *)d_in[1];
    float *out = (float *)d_out;

    static int inited = 0;
    if (!inited) {
        cudaFuncSetAttribute(knn_hmma_kernel, cudaFuncAttributeMaxDynamicSharedMemorySize,
                             SMEM_KNN);
        inited = 1;
    }

    split_kernel<<<N_PTS * DIM / 4 / 256, 256>>>(x);
    sq_kernel<<<N_PTS / 8, TPB>>>(x);
    xw_kernel<<<dim3(N_PTS / BM, OUT_D / BN), TPB>>>(x, A);
    knn_hmma_kernel<<<N_PTS / 128, TPB, SMEM_KNN>>>();
    rescore_kernel<<<N_PTS, 512>>>(x, out);
}

// round 9
// speedup vs baseline: 1.0133x; 1.0133x over previous
#include <cuda_runtime.h>
#include <cuda_bf16.h>
#include <cstdint>

#define N_PTS 16384
#define DIM   512
#define OUT_D 512
#define KNN   10
#define NCAND 16

// fp32 xw tiling
#define BM 128
#define BN 128
#define KCH 32
#define TPB 256
#define LDS_ 132

#define INF_F __int_as_float(0x7f800000)

__device__ float g_sq[N_PTS];
__device__ float g_xW[N_PTS * OUT_D];
__device__ __nv_bfloat16 g_hi[(size_t)N_PTS * DIM];
__device__ int g_cand[N_PTS * NCAND];

// ---------------- helpers ----------------
__device__ __forceinline__ uint32_t smem_u32(const void *p) {
    uint32_t a;
    asm("{ .reg .u64 t; cvta.to.shared.u64 t, %1; cvt.u32.u64 %0, t; }" : "=r"(a) : "l"(p));
    return a;
}
#define SW128(o) ((o) ^ (((o) >> 3) & 0x70))

__device__ __forceinline__ void cp_async16(uint32_t dst, const void *src) {
    asm volatile("cp.async.cg.shared.global [%0], [%1], 16;" :: "r"(dst), "l"(src) : "memory");
}
#define CP_COMMIT() asm volatile("cp.async.commit_group;" ::: "memory")
#define CP_WAIT(n)  asm volatile("cp.async.wait_group %0;" :: "n"(n) : "memory")

__device__ __forceinline__ void ldsm4(uint32_t &r0, uint32_t &r1, uint32_t &r2, uint32_t &r3,
                                      uint32_t addr) {
    asm volatile("ldmatrix.sync.aligned.m8n8.x4.shared.b16 {%0,%1,%2,%3}, [%4];"
                 : "=r"(r0), "=r"(r1), "=r"(r2), "=r"(r3) : "r"(addr));
}
__device__ __forceinline__ void mma_bf16(float &c0, float &c1, float &c2, float &c3,
                                         uint32_t a0, uint32_t a1, uint32_t a2, uint32_t a3,
                                         uint32_t b0, uint32_t b1) {
    asm volatile("mma.sync.aligned.m16n8k16.row.col.f32.bf16.bf16.f32 "
                 "{%0,%1,%2,%3}, {%4,%5,%6,%7}, {%8,%9}, {%0,%1,%2,%3};"
                 : "+f"(c0), "+f"(c1), "+f"(c2), "+f"(c3)
                 : "r"(a0), "r"(a1), "r"(a2), "r"(a3), "r"(b0), "r"(b1));
}

// ---------------- split: x -> bf16 hi ----------------
__global__ void __launch_bounds__(256) split_kernel(const float *__restrict__ x) {
    int t = blockIdx.x * 256 + threadIdx.x;
    float4 v = *(const float4 *)(x + (size_t)t * 4);
    __nv_bfloat162 p0, p1;
    p0.x = __float2bfloat16_rn(v.x); p0.y = __float2bfloat16_rn(v.y);
    p1.x = __float2bfloat16_rn(v.z); p1.y = __float2bfloat16_rn(v.w);
    __nv_bfloat16 *o = g_hi + (size_t)t * 4;
    *(__nv_bfloat162 *)(o) = p0;
    *(__nv_bfloat162 *)(o + 2) = p1;
}

// ---------------- row squared norms ----------------
__global__ void sq_kernel(const float *__restrict__ x) {
    int row = blockIdx.x * 8 + (threadIdx.x >> 5);
    int lane = threadIdx.x & 31;
    const float4 *xr = (const float4 *)(x + (long)row * DIM);
    float s = 0.f;
#pragma unroll
    for (int i = 0; i < 4; i++) {
        float4 v = xr[lane + i * 32];
        s += v.x * v.x + v.y * v.y + v.z * v.z + v.w * v.w;
    }
#pragma unroll
    for (int o = 16; o; o >>= 1) s += __shfl_xor_sync(0xFFFFFFFFu, s, o);
    if (lane == 0) g_sq[row] = s;
}

// ---------------- fp32 xW = x @ A ----------------
__device__ __forceinline__ unsigned long long pack2(float x, float y) {
    unsigned long long r; asm("mov.b64 %0, {%1, %2};" : "=l"(r) : "f"(x), "f"(y)); return r;
}
__device__ __forceinline__ void unpack2(unsigned long long v, float &a, float &b) {
    asm("mov.b64 {%0, %1}, %2;" : "=f"(a), "=f"(b) : "l"(v));
}
__device__ __forceinline__ void fma2(unsigned long long &d, unsigned long long a, unsigned long long b) {
    asm("fma.rn.f32x2 %0, %1, %2, %0;" : "+l"(d) : "l"(a), "l"(b));
}
__device__ __forceinline__ void load_T(float *dst, const float *__restrict__ src, int row0, int kc, int ld) {
    int t = threadIdx.x;
#pragma unroll
    for (int i = 0; i < 4; i++) {
        int idx = t + i * TPB, r = idx >> 3, f4 = idx & 7;
        float4 v = *(const float4 *)(src + (long)(row0 + r) * ld + kc + f4 * 4);
        dst[(f4 * 4 + 0) * LDS_ + r] = v.x; dst[(f4 * 4 + 1) * LDS_ + r] = v.y;
        dst[(f4 * 4 + 2) * LDS_ + r] = v.z; dst[(f4 * 4 + 3) * LDS_ + r] = v.w;
    }
}
__device__ __forceinline__ void load_N(float *dst, const float *__restrict__ src, int kc, int col0, int ld) {
    int t = threadIdx.x;
#pragma unroll
    for (int i = 0; i < 4; i++) {
        int idx = t + i * TPB, kk = idx >> 5, c4 = idx & 31;
        float4 v = *(const float4 *)(src + (long)(kc + kk) * ld + col0 + c4 * 4);
        *(float4 *)(dst + kk * LDS_ + c4 * 4) = v;
    }
}
__global__ void __launch_bounds__(TPB) xw_kernel(const float *__restrict__ x, const float *__restrict__ A) {
    __shared__ float Xs[KCH * LDS_], Ws[KCH * LDS_];
    int m0 = blockIdx.x * BM, n0 = blockIdx.y * BN;
    int w = threadIdx.x >> 5, l = threadIdx.x & 31;
    int tx = (l & 7) | ((w & 1) << 3), ty = (l >> 3) | ((w >> 1) << 2);
    unsigned long long acc[8][4];
#pragma unroll
    for (int i = 0; i < 8; i++)
#pragma unroll
        for (int j = 0; j < 4; j++) acc[i][j] = 0ull;
    for (int kc = 0; kc < DIM; kc += KCH) {
        __syncthreads();
        load_T(Xs, x, m0, kc, DIM);
        load_N(Ws, A, kc, n0, OUT_D);
        __syncthreads();
#pragma unroll 8
        for (int kk = 0; kk < KCH; kk++) {
            const float *ar = Xs + kk * LDS_ + ty * 8;
            const float *br = Ws + kk * LDS_ + tx * 8;
            unsigned long long b2[4], a2[8];
#pragma unroll
            for (int j = 0; j < 4; j++) b2[j] = *(const unsigned long long *)(br + j * 2);
#pragma unroll
            for (int i = 0; i < 8; i++) { float av = ar[i]; a2[i] = pack2(av, av); }
#pragma unroll
            for (int i = 0; i < 8; i++)
#pragma unroll
                for (int j = 0; j < 4; j++) fma2(acc[i][j], a2[i], b2[j]);
        }
    }
#pragma unroll
    for (int i = 0; i < 8; i++) {
        int m = m0 + ty * 8 + i;
#pragma unroll
        for (int j = 0; j < 4; j++) {
            float v0, v1; unpack2(acc[i][j], v0, v1);
            int n = n0 + tx * 8 + j * 2;
            g_xW[(long)m * OUT_D + n] = v0;
            g_xW[(long)m * OUT_D + n + 1] = v1;
        }
    }
}

// ---------------- HMMA bf16 distance sweep + approx top-16 ----------------
// R5 shape frozen: 256 threads, warp grid 2(M)x4(N), warp tile 64x32, A resident.
// Only change: B pipeline 2 -> 3 stages (16KB each), CP_WAIT(1) in steady state.
// smem: A 128KB | B 3x16KB | Ds 128x68 f32 | sqj 512B  = 216,064 B
#define SM_A   0
#define SM_B   131072
#define SM_DS  180224
#define SM_SQJ 215040
#define SMEM_KNN 215552
#define DS_STRIDE 68

__global__ void __launch_bounds__(256, 1) knn_hmma_kernel() {
    extern __shared__ char sm[];
    uint32_t sb = smem_u32(sm);
    float *Ds = (float *)(sm + SM_DS);
    float *sqj_s = (float *)(sm + SM_SQJ);

    int tid = threadIdx.x;
    int lane = tid & 31, w = tid >> 5;
    int wm = w >> 2, wn = w & 3;          // warp grid 2(M) x 4(N)
    int hme = wn >> 1;                    // which 64-col half this warp outputs
    int r0 = blockIdx.x * 128;

    int lrow = lane & 15;
    int lkp  = (lane >> 4) * 8;

    // ---- preload full A tile (8 k-blocks) + B chunks q=0 and q=1 ----
    {
        const __nv_bfloat16 *Ab = g_hi + (size_t)r0 * DIM;
#pragma unroll
        for (int u = 0; u < 32; u++) {
            int g = tid + u * 256;
            int kblk = g >> 10, rem = g & 1023;
            int row = rem >> 3, k8 = (rem & 7) * 8;
            uint32_t dst = sb + SM_A + kblk * 16384 + SW128(row * 128 + k8 * 2);
            cp_async16(dst, Ab + (size_t)row * DIM + kblk * 64 + k8);
        }
        CP_COMMIT();
#pragma unroll
        for (int c0 = 0; c0 < 2; c0++) {      // chunk q=0 (kb=0) and q=1 (kb=1), j=0
#pragma unroll
            for (int u = 0; u < 4; u++) {
                int g = tid + u * 256;
                int row = g >> 3, k8 = (g & 7) * 8;
                uint32_t dst = sb + SM_B + c0 * 16384 + SW128(row * 128 + k8 * 2);
                cp_async16(dst, g_hi + (size_t)row * DIM + c0 * 64 + k8);
            }
            CP_COMMIT();
        }
    }

    float bd[NCAND];
    int bi[NCAND];
#pragma unroll
    for (int k = 0; k < NCAND; k++) { bd[k] = INF_F; bi[k] = -1; }
    float th = INF_F;

    for (int j = 0; j < 128; j++) {
        float acc[4][4][4];
#pragma unroll
        for (int a = 0; a < 4; a++)
#pragma unroll
            for (int b = 0; b < 4; b++)
#pragma unroll
                for (int c = 0; c < 4; c++) acc[a][b][c] = 0.f;

        for (int kb = 0; kb < 8; kb++) {
            int q = j * 8 + kb;
            int stage = q % 3;

            if (q + 1 < 1024) { CP_WAIT(1); } else { CP_WAIT(0); }
            __syncthreads();
            if (kb == 0 && tid < 128) sqj_s[tid] = g_sq[j * 128 + tid];

            if (q + 2 < 1024) {
                int qn = q + 2;
                int jn = qn >> 3, kbn = qn & 7, sn = qn % 3;
#pragma unroll
                for (int u = 0; u < 4; u++) {
                    int g = tid + u * 256;
                    int row = g >> 3, k8 = (g & 7) * 8;
                    uint32_t dst = sb + SM_B + sn * 16384 + SW128(row * 128 + k8 * 2);
                    cp_async16(dst, g_hi + (size_t)(jn * 128 + row) * DIM + kbn * 64 + k8);
                }
                CP_COMMIT();
            }

            uint32_t Ab = sb + SM_A + kb * 16384;
            uint32_t Bb = sb + SM_B + stage * 16384;
#pragma unroll
            for (int ks = 0; ks < 4; ks++) {
                int koff = ks * 16 + lkp;
                uint32_t b0, b1, b2, b3, b4, b5, b6, b7;
                {
                    int n = wn * 32 + lrow;
                    ldsm4(b0, b1, b2, b3, Bb + SW128(n * 128 + koff * 2));
                    ldsm4(b4, b5, b6, b7, Bb + SW128((n + 16) * 128 + koff * 2));
                }
#pragma unroll
                for (int mb = 0; mb < 4; mb++) {
                    uint32_t a0, a1, a2, a3;
                    int m = wm * 64 + mb * 16 + lrow;
                    ldsm4(a0, a1, a2, a3, Ab + SW128(m * 128 + koff * 2));
                    mma_bf16(acc[mb][0][0], acc[mb][0][1], acc[mb][0][2], acc[mb][0][3],
                             a0, a1, a2, a3, b0, b2);
                    mma_bf16(acc[mb][1][0], acc[mb][1][1], acc[mb][1][2], acc[mb][1][3],
                             a0, a1, a2, a3, b1, b3);
                    mma_bf16(acc[mb][2][0], acc[mb][2][1], acc[mb][2][2], acc[mb][2][3],
                             a0, a1, a2, a3, b4, b6);
                    mma_bf16(acc[mb][3][0], acc[mb][3][1], acc[mb][3][2], acc[mb][3][3],
                             a0, a1, a2, a3, b5, b7);
                }
            }
        }

        // ---- epilogue: two 64-col halves through Ds ----
#pragma unroll
        for (int half = 0; half < 2; half++) {
            __syncthreads();
            if (hme == half) {
#pragma unroll
                for (int mb = 0; mb < 4; mb++) {
                    int r1 = wm * 64 + mb * 16 + (lane >> 2);
#pragma unroll
                    for (int nb = 0; nb < 4; nb++) {
                        int cb = (wn & 1) * 32 + nb * 8 + (lane & 3) * 2;
                        float2 v0, v1;
                        v0.x = acc[mb][nb][0]; v0.y = acc[mb][nb][1];
                        v1.x = acc[mb][nb][2]; v1.y = acc[mb][nb][3];
                        *(float2 *)(Ds + r1 * DS_STRIDE + cb) = v0;
                        *(float2 *)(Ds + (r1 + 8) * DS_STRIDE + cb) = v1;
                    }
                }
            }
            __syncthreads();
            {
                int row = tid & 127, seg = tid >> 7;
                int gm = r0 + row;
                const float *dr = Ds + row * DS_STRIDE + seg * 32;
                int ctile = half * 64 + seg * 32;
                int jb = j * 128 + ctile;
#pragma unroll 4
                for (int c4 = 0; c4 < 8; c4++) {
                    float4 v = *(const float4 *)(dr + c4 * 4);
                    const float *sq4 = sqj_s + ctile + c4 * 4;
                    int cb = jb + c4 * 4;
                    float s0 = sq4[0] - 2.0f * v.x;
                    float s1 = sq4[1] - 2.0f * v.y;
                    float s2 = sq4[2] - 2.0f * v.z;
                    float s3 = sq4[3] - 2.0f * v.w;
                    if (s0 < th && cb + 0 != gm) {
                        int p = NCAND - 1;
                        while (p > 0 && bd[p - 1] > s0) { bd[p] = bd[p - 1]; bi[p] = bi[p - 1]; p--; }
                        bd[p] = s0; bi[p] = cb + 0; th = bd[NCAND - 1];
                    }
                    if (s1 < th && cb + 1 != gm) {
                        int p = NCAND - 1;
                        while (p > 0 && bd[p - 1] > s1) { bd[p] = bd[p - 1]; bi[p] = bi[p - 1]; p--; }
                        bd[p] = s1; bi[p] = cb + 1; th = bd[NCAND - 1];
                    }
                    if (s2 < th && cb + 2 != gm) {
                        int p = NCAND - 1;
                        while (p > 0 && bd[p - 1] > s2) { bd[p] = bd[p - 1]; bi[p] = bi[p - 1]; p--; }
                        bd[p] = s2; bi[p] = cb + 2; th = bd[NCAND - 1];
                    }
                    if (s3 < th && cb + 3 != gm) {
                        int p = NCAND - 1;
                        while (p > 0 && bd[p - 1] > s3) { bd[p] = bd[p - 1]; bi[p] = bi[p - 1]; p--; }
                        bd[p] = s3; bi[p] = cb + 3; th = bd[NCAND - 1];
                    }
                }
            }
        }
    }

    // ---- merge the two per-row half-lists (both sorted), emit top-16 ----
    __syncthreads();
    float *md = Ds;
    int *mi = (int *)(Ds + 4096);
#pragma unroll
    for (int k = 0; k < NCAND; k++) {
        md[tid * NCAND + k] = bd[k];
        mi[tid * NCAND + k] = bi[k];
    }
    __syncthreads();
    if (tid < 128) {
        const float *da = md + tid * NCAND;
        const int *ia = mi + tid * NCAND;
        const float *db = md + (tid + 128) * NCAND;
        const int *ib = mi + (tid + 128) * NCAND;
        int pa = 0, pb = 0;
#pragma unroll
        for (int k = 0; k < NCAND; k++) {
            float va = da[pa], vb = db[pb];
            bool takeA = (va < vb) || (va == vb && ia[pa] < ib[pb]);
            int sel = takeA ? ia[pa] : ib[pb];
            if (takeA) pa++; else pb++;
            g_cand[(r0 + tid) * NCAND + k] = sel;
        }
    }
}

// ---------------- exact fp32 rescore + gather-sum ----------------
__global__ void __launch_bounds__(512) rescore_kernel(const float *__restrict__ x,
                                                      float *__restrict__ out) {
    __shared__ float xr[512];
    __shared__ float cd[NCAND];
    __shared__ int ci[NCAND];
    __shared__ int sel[KNN];
    int row = blockIdx.x;
    int tid = threadIdx.x;
    int w = tid >> 5, lane = tid & 31;
    xr[tid] = x[(long)row * DIM + tid];
    if (tid < NCAND) ci[tid] = g_cand[row * NCAND + tid];
    __syncthreads();
    {
        int c = ci[w];
        float s = 0.f;
        if (c >= 0) {
            const float *xc = x + (long)c * DIM;
#pragma unroll
            for (int t = 0; t < 16; t++) {
                int e = lane + 32 * t;
                s += xr[e] * xc[e];
            }
        }
#pragma unroll
        for (int o = 16; o; o >>= 1) s += __shfl_xor_sync(0xFFFFFFFFu, s, o);
        if (lane == 0) cd[w] = (c >= 0) ? (g_sq[row] + g_sq[c] - 2.0f * s) : INF_F;
    }
    __syncthreads();
    if (tid == 0) {
        unsigned used = 0;
        for (int k = 0; k < KNN; k++) {
            float best = INF_F; int bidx = 0x7FFFFFFF, bw = 0;
            for (int q = 0; q < NCAND; q++) {
                if (used & (1u << q)) continue;
                float d = cd[q]; int id = ci[q];
                if (d < best || (d == best && id < bidx)) { best = d; bidx = id; bw = q; }
            }
            used |= 1u << bw;
            sel[k] = bidx;
        }
    }
    __syncthreads();
    float s = 0.f;
#pragma unroll
    for (int k = 0; k < KNN; k++) s += g_xW[(long)sel[k] * OUT_D + tid];
    out[(long)row * OUT_D + tid] = s;
}

// ---------------- launcher ----------------
extern "C" void kernel_launch(void *const *d_in, const int *in_sizes, int n_in,
                              void *d_out, int out_size) {
    const float *x = (const float *)d_in[0];
    const float *A = (const float *)d_in[1];
    float *out = (float *)d_out;

    static int inited = 0;
    if (!inited) {
        cudaFuncSetAttribute(knn_hmma_kernel, cudaFuncAttributeMaxDynamicSharedMemorySize,
                             SMEM_KNN);
        inited = 1;
    }

    split_kernel<<<N_PTS * DIM / 4 / 256, 256>>>(x);
    sq_kernel<<<N_PTS / 8, TPB>>>(x);
    xw_kernel<<<dim3(N_PTS / BM, OUT_D / BN), TPB>>>(x, A);
    knn_hmma_kernel<<<N_PTS / 128, TPB, SMEM_KNN>>>();
    rescore_kernel<<<N_PTS, 512>>>(x, out);
}

// round 10
// speedup vs baseline: 1.1438x; 1.1288x over previous
#include <cuda_runtime.h>
#include <cuda_bf16.h>
#include <cstdint>

#define N_PTS 16384
#define DIM   512
#define OUT_D 512
#define KNN   10
#define NCAND 16

// fp32 xw tiling
#define BM 128
#define BN 128
#define KCH 32
#define TPB 256
#define LDS_ 132

#define INF_F __int_as_float(0x7f800000)

__device__ float g_sq[N_PTS];
__device__ float g_xW[N_PTS * OUT_D];
__device__ __nv_bfloat16 g_hi[(size_t)N_PTS * DIM];
__device__ int g_cand[N_PTS * NCAND];

// ---------------- helpers ----------------
__device__ __forceinline__ uint32_t smem_u32(const void *p) {
    uint32_t a;
    asm("{ .reg .u64 t; cvta.to.shared.u64 t, %1; cvt.u32.u64 %0, t; }" : "=r"(a) : "l"(p));
    return a;
}
#define SW128(o) ((o) ^ (((o) >> 3) & 0x70))

__device__ __forceinline__ void cp_async16(uint32_t dst, const void *src) {
    asm volatile("cp.async.cg.shared.global [%0], [%1], 16;" :: "r"(dst), "l"(src) : "memory");
}
#define CP_COMMIT() asm volatile("cp.async.commit_group;" ::: "memory")
#define CP_WAIT(n)  asm volatile("cp.async.wait_group %0;" :: "n"(n) : "memory")

__device__ __forceinline__ void ldsm4(uint32_t &r0, uint32_t &r1, uint32_t &r2, uint32_t &r3,
                                      uint32_t addr) {
    asm volatile("ldmatrix.sync.aligned.m8n8.x4.shared.b16 {%0,%1,%2,%3}, [%4];"
                 : "=r"(r0), "=r"(r1), "=r"(r2), "=r"(r3) : "r"(addr));
}
__device__ __forceinline__ void mma_bf16(float &c0, float &c1, float &c2, float &c3,
                                         uint32_t a0, uint32_t a1, uint32_t a2, uint32_t a3,
                                         uint32_t b0, uint32_t b1) {
    asm volatile("mma.sync.aligned.m16n8k16.row.col.f32.bf16.bf16.f32 "
                 "{%0,%1,%2,%3}, {%4,%5,%6,%7}, {%8,%9}, {%0,%1,%2,%3};"
                 : "+f"(c0), "+f"(c1), "+f"(c2), "+f"(c3)
                 : "r"(a0), "r"(a1), "r"(a2), "r"(a3), "r"(b0), "r"(b1));
}

// ---------------- split: x -> bf16 hi ----------------
__global__ void __launch_bounds__(256) split_kernel(const float *__restrict__ x) {
    int t = blockIdx.x * 256 + threadIdx.x;
    float4 v = *(const float4 *)(x + (size_t)t * 4);
    __nv_bfloat162 p0, p1;
    p0.x = __float2bfloat16_rn(v.x); p0.y = __float2bfloat16_rn(v.y);
    p1.x = __float2bfloat16_rn(v.z); p1.y = __float2bfloat16_rn(v.w);
    __nv_bfloat16 *o = g_hi + (size_t)t * 4;
    *(__nv_bfloat162 *)(o) = p0;
    *(__nv_bfloat162 *)(o + 2) = p1;
}

// ---------------- row squared norms ----------------
__global__ void sq_kernel(const float *__restrict__ x) {
    int row = blockIdx.x * 8 + (threadIdx.x >> 5);
    int lane = threadIdx.x & 31;
    const float4 *xr = (const float4 *)(x + (long)row * DIM);
    float s = 0.f;
#pragma unroll
    for (int i = 0; i < 4; i++) {
        float4 v = xr[lane + i * 32];
        s += v.x * v.x + v.y * v.y + v.z * v.z + v.w * v.w;
    }
#pragma unroll
    for (int o = 16; o; o >>= 1) s += __shfl_xor_sync(0xFFFFFFFFu, s, o);
    if (lane == 0) g_sq[row] = s;
}

// ---------------- fp32 xW = x @ A ----------------
__device__ __forceinline__ unsigned long long pack2(float x, float y) {
    unsigned long long r; asm("mov.b64 %0, {%1, %2};" : "=l"(r) : "f"(x), "f"(y)); return r;
}
__device__ __forceinline__ void unpack2(unsigned long long v, float &a, float &b) {
    asm("mov.b64 {%0, %1}, %2;" : "=f"(a), "=f"(b) : "l"(v));
}
__device__ __forceinline__ void fma2(unsigned long long &d, unsigned long long a, unsigned long long b) {
    asm("fma.rn.f32x2 %0, %1, %2, %0;" : "+l"(d) : "l"(a), "l"(b));
}
__device__ __forceinline__ void load_T(float *dst, const float *__restrict__ src, int row0, int kc, int ld) {
    int t = threadIdx.x;
#pragma unroll
    for (int i = 0; i < 4; i++) {
        int idx = t + i * TPB, r = idx >> 3, f4 = idx & 7;
        float4 v = *(const float4 *)(src + (long)(row0 + r) * ld + kc + f4 * 4);
        dst[(f4 * 4 + 0) * LDS_ + r] = v.x; dst[(f4 * 4 + 1) * LDS_ + r] = v.y;
        dst[(f4 * 4 + 2) * LDS_ + r] = v.z; dst[(f4 * 4 + 3) * LDS_ + r] = v.w;
    }
}
__device__ __forceinline__ void load_N(float *dst, const float *__restrict__ src, int kc, int col0, int ld) {
    int t = threadIdx.x;
#pragma unroll
    for (int i = 0; i < 4; i++) {
        int idx = t + i * TPB, kk = idx >> 5, c4 = idx & 31;
        float4 v = *(const float4 *)(src + (long)(kc + kk) * ld + col0 + c4 * 4);
        *(float4 *)(dst + kk * LDS_ + c4 * 4) = v;
    }
}
__global__ void __launch_bounds__(TPB) xw_kernel(const float *__restrict__ x, const float *__restrict__ A) {
    __shared__ float Xs[KCH * LDS_], Ws[KCH * LDS_];
    int m0 = blockIdx.x * BM, n0 = blockIdx.y * BN;
    int w = threadIdx.x >> 5, l = threadIdx.x & 31;
    int tx = (l & 7) | ((w & 1) << 3), ty = (l >> 3) | ((w >> 1) << 2);
    unsigned long long acc[8][4];
#pragma unroll
    for (int i = 0; i < 8; i++)
#pragma unroll
        for (int j = 0; j < 4; j++) acc[i][j] = 0ull;
    for (int kc = 0; kc < DIM; kc += KCH) {
        __syncthreads();
        load_T(Xs, x, m0, kc, DIM);
        load_N(Ws, A, kc, n0, OUT_D);
        __syncthreads();
#pragma unroll 8
        for (int kk = 0; kk < KCH; kk++) {
            const float *ar = Xs + kk * LDS_ + ty * 8;
            const float *br = Ws + kk * LDS_ + tx * 8;
            unsigned long long b2[4], a2[8];
#pragma unroll
            for (int j = 0; j < 4; j++) b2[j] = *(const unsigned long long *)(br + j * 2);
#pragma unroll
            for (int i = 0; i < 8; i++) { float av = ar[i]; a2[i] = pack2(av, av); }
#pragma unroll
            for (int i = 0; i < 8; i++)
#pragma unroll
                for (int j = 0; j < 4; j++) fma2(acc[i][j], a2[i], b2[j]);
        }
    }
#pragma unroll
    for (int i = 0; i < 8; i++) {
        int m = m0 + ty * 8 + i;
#pragma unroll
        for (int j = 0; j < 4; j++) {
            float v0, v1; unpack2(acc[i][j], v0, v1);
            int n = n0 + tx * 8 + j * 2;
            g_xW[(long)m * OUT_D + n] = v0;
            g_xW[(long)m * OUT_D + n + 1] = v1;
        }
    }
}

// ---------------- HMMA bf16 distance sweep + approx top-16 ----------------
// Mainloop byte-identical to R5 (256 threads, warp grid 2x4, warp tile 64x32,
// A resident, B 2x16KB, wait->sync->prefetch->MMA). Epilogue merged: single
// full-width Ds phase (128x132 f32) -> 2 barriers/tile instead of 4.
// smem: A 128KB | B 2x16KB | Ds 128x132 f32 (67584) | sqj 512B = 231,936 B
#define SM_A   0
#define SM_B   131072
#define SM_DS  163840
#define SM_SQJ 231424
#define SMEM_KNN 231936
#define DS_STRIDE 132

__global__ void __launch_bounds__(256, 1) knn_hmma_kernel() {
    extern __shared__ char sm[];
    uint32_t sb = smem_u32(sm);
    float *Ds = (float *)(sm + SM_DS);
    float *sqj_s = (float *)(sm + SM_SQJ);

    int tid = threadIdx.x;
    int lane = tid & 31, w = tid >> 5;
    int wm = w >> 2, wn = w & 3;          // warp grid 2(M) x 4(N)
    int r0 = blockIdx.x * 128;

    int lrow = lane & 15;
    int lkp  = (lane >> 4) * 8;

    // ---- preload full A tile (8 k-blocks) + B chunk q=0 ----
    {
        const __nv_bfloat16 *Ab = g_hi + (size_t)r0 * DIM;
#pragma unroll
        for (int u = 0; u < 32; u++) {
            int g = tid + u * 256;
            int kblk = g >> 10, rem = g & 1023;
            int row = rem >> 3, k8 = (rem & 7) * 8;
            uint32_t dst = sb + SM_A + kblk * 16384 + SW128(row * 128 + k8 * 2);
            cp_async16(dst, Ab + (size_t)row * DIM + kblk * 64 + k8);
        }
        CP_COMMIT();
#pragma unroll
        for (int u = 0; u < 4; u++) {
            int g = tid + u * 256;
            int row = g >> 3, k8 = (g & 7) * 8;
            uint32_t dst = sb + SM_B + SW128(row * 128 + k8 * 2);
            cp_async16(dst, g_hi + (size_t)row * DIM + k8);   // j=0, kb=0
        }
        CP_COMMIT();
    }

    float bd[NCAND];
    int bi[NCAND];
#pragma unroll
    for (int k = 0; k < NCAND; k++) { bd[k] = INF_F; bi[k] = -1; }
    float th = INF_F;

    for (int j = 0; j < 128; j++) {
        float acc[4][4][4];
#pragma unroll
        for (int a = 0; a < 4; a++)
#pragma unroll
            for (int b = 0; b < 4; b++)
#pragma unroll
                for (int c = 0; c < 4; c++) acc[a][b][c] = 0.f;

        for (int kb = 0; kb < 8; kb++) {
            int q = j * 8 + kb;
            int stage = q & 1;

            CP_WAIT(0);
            __syncthreads();
            if (kb == 0 && tid < 128) sqj_s[tid] = g_sq[j * 128 + tid];

            if (q + 1 < 1024) {
                int qn = q + 1;
                int jn = qn >> 3, kbn = qn & 7, sn = qn & 1;
#pragma unroll
                for (int u = 0; u < 4; u++) {
                    int g = tid + u * 256;
                    int row = g >> 3, k8 = (g & 7) * 8;
                    uint32_t dst = sb + SM_B + sn * 16384 + SW128(row * 128 + k8 * 2);
                    cp_async16(dst, g_hi + (size_t)(jn * 128 + row) * DIM + kbn * 64 + k8);
                }
                CP_COMMIT();
            }

            uint32_t Ab = sb + SM_A + kb * 16384;
            uint32_t Bb = sb + SM_B + stage * 16384;
#pragma unroll
            for (int ks = 0; ks < 4; ks++) {
                int koff = ks * 16 + lkp;
                uint32_t b0, b1, b2, b3, b4, b5, b6, b7;
                {
                    int n = wn * 32 + lrow;
                    ldsm4(b0, b1, b2, b3, Bb + SW128(n * 128 + koff * 2));
                    ldsm4(b4, b5, b6, b7, Bb + SW128((n + 16) * 128 + koff * 2));
                }
#pragma unroll
                for (int mb = 0; mb < 4; mb++) {
                    uint32_t a0, a1, a2, a3;
                    int m = wm * 64 + mb * 16 + lrow;
                    ldsm4(a0, a1, a2, a3, Ab + SW128(m * 128 + koff * 2));
                    mma_bf16(acc[mb][0][0], acc[mb][0][1], acc[mb][0][2], acc[mb][0][3],
                             a0, a1, a2, a3, b0, b2);
                    mma_bf16(acc[mb][1][0], acc[mb][1][1], acc[mb][1][2], acc[mb][1][3],
                             a0, a1, a2, a3, b1, b3);
                    mma_bf16(acc[mb][2][0], acc[mb][2][1], acc[mb][2][2], acc[mb][2][3],
                             a0, a1, a2, a3, b4, b6);
                    mma_bf16(acc[mb][3][0], acc[mb][3][1], acc[mb][3][2], acc[mb][3][3],
                             a0, a1, a2, a3, b5, b7);
                }
            }
        }

        // ---- merged epilogue: one full-width phase, 2 barriers ----
        __syncthreads();                      // prior scan done reading Ds
#pragma unroll
        for (int mb = 0; mb < 4; mb++) {
            int r1 = wm * 64 + mb * 16 + (lane >> 2);
#pragma unroll
            for (int nb = 0; nb < 4; nb++) {
                int cb = wn * 32 + nb * 8 + (lane & 3) * 2;
                float2 v0, v1;
                v0.x = acc[mb][nb][0]; v0.y = acc[mb][nb][1];
                v1.x = acc[mb][nb][2]; v1.y = acc[mb][nb][3];
                *(float2 *)(Ds + r1 * DS_STRIDE + cb) = v0;
                *(float2 *)(Ds + (r1 + 8) * DS_STRIDE + cb) = v1;
            }
        }
        __syncthreads();
        // scan: thread -> (row = tid&127, seg = tid>>7), 64 cols per seg
        {
            int row = tid & 127, seg = tid >> 7;
            int gm = r0 + row;
            const float *dr = Ds + row * DS_STRIDE + seg * 64;
            int ctile = seg * 64;
            int jb = j * 128 + ctile;
#pragma unroll 4
            for (int c4 = 0; c4 < 16; c4++) {
                float4 v = *(const float4 *)(dr + c4 * 4);
                const float *sq4 = sqj_s + ctile + c4 * 4;
                int cb = jb + c4 * 4;
                float s0 = sq4[0] - 2.0f * v.x;
                float s1 = sq4[1] - 2.0f * v.y;
                float s2 = sq4[2] - 2.0f * v.z;
                float s3 = sq4[3] - 2.0f * v.w;
                if (s0 < th && cb + 0 != gm) {
                    int p = NCAND - 1;
                    while (p > 0 && bd[p - 1] > s0) { bd[p] = bd[p - 1]; bi[p] = bi[p - 1]; p--; }
                    bd[p] = s0; bi[p] = cb + 0; th = bd[NCAND - 1];
                }
                if (s1 < th && cb + 1 != gm) {
                    int p = NCAND - 1;
                    while (p > 0 && bd[p - 1] > s1) { bd[p] = bd[p - 1]; bi[p] = bi[p - 1]; p--; }
                    bd[p] = s1; bi[p] = cb + 1; th = bd[NCAND - 1];
                }
                if (s2 < th && cb + 2 != gm) {
                    int p = NCAND - 1;
                    while (p > 0 && bd[p - 1] > s2) { bd[p] = bd[p - 1]; bi[p] = bi[p - 1]; p--; }
                    bd[p] = s2; bi[p] = cb + 2; th = bd[NCAND - 1];
                }
                if (s3 < th && cb + 3 != gm) {
                    int p = NCAND - 1;
                    while (p > 0 && bd[p - 1] > s3) { bd[p] = bd[p - 1]; bi[p] = bi[p - 1]; p--; }
                    bd[p] = s3; bi[p] = cb + 3; th = bd[NCAND - 1];
                }
            }
        }
    }

    // ---- merge the two per-row half-lists (both sorted), emit top-16 ----
    __syncthreads();
    float *md = Ds;
    int *mi = (int *)(Ds + 4096);
#pragma unroll
    for (int k = 0; k < NCAND; k++) {
        md[tid * NCAND + k] = bd[k];
        mi[tid * NCAND + k] = bi[k];
    }
    __syncthreads();
    if (tid < 128) {
        const float *da = md + tid * NCAND;
        const int *ia = mi + tid * NCAND;
        const float *db = md + (tid + 128) * NCAND;
        const int *ib = mi + (tid + 128) * NCAND;
        int pa = 0, pb = 0;
#pragma unroll
        for (int k = 0; k < NCAND; k++) {
            float va = da[pa], vb = db[pb];
            bool takeA = (va < vb) || (va == vb && ia[pa] < ib[pb]);
            int sel = takeA ? ia[pa] : ib[pb];
            if (takeA) pa++; else pb++;
            g_cand[(r0 + tid) * NCAND + k] = sel;
        }
    }
}

// ---------------- exact fp32 rescore + gather-sum ----------------
__global__ void __launch_bounds__(512) rescore_kernel(const float *__restrict__ x,
                                                      float *__restrict__ out) {
    __shared__ float xr[512];
    __shared__ float cd[NCAND];
    __shared__ int ci[NCAND];
    __shared__ int sel[KNN];
    int row = blockIdx.x;
    int tid = threadIdx.x;
    int w = tid >> 5, lane = tid & 31;
    xr[tid] = x[(long)row * DIM + tid];
    if (tid < NCAND) ci[tid] = g_cand[row * NCAND + tid];
    __syncthreads();
    {
        int c = ci[w];
        float s = 0.f;
        if (c >= 0) {
            const float *xc = x + (long)c * DIM;
#pragma unroll
            for (int t = 0; t < 16; t++) {
                int e = lane + 32 * t;
                s += xr[e] * xc[e];
            }
        }
#pragma unroll
        for (int o = 16; o; o >>= 1) s += __shfl_xor_sync(0xFFFFFFFFu, s, o);
        if (lane == 0) cd[w] = (c >= 0) ? (g_sq[row] + g_sq[c] - 2.0f * s) : INF_F;
    }
    __syncthreads();
    if (tid == 0) {
        unsigned used = 0;
        for (int k = 0; k < KNN; k++) {
            float best = INF_F; int bidx = 0x7FFFFFFF, bw = 0;
            for (int q = 0; q < NCAND; q++) {
                if (used & (1u << q)) continue;
                float d = cd[q]; int id = ci[q];
                if (d < best || (d == best && id < bidx)) { best = d; bidx = id; bw = q; }
            }
            used |= 1u << bw;
            sel[k] = bidx;
        }
    }
    __syncthreads();
    float s = 0.f;
#pragma unroll
    for (int k = 0; k < KNN; k++) s += g_xW[(long)sel[k] * OUT_D + tid];
    out[(long)row * OUT_D + tid] = s;
}

// ---------------- launcher ----------------
extern "C" void kernel_launch(void *const *d_in, const int *in_sizes, int n_in,
                              void *d_out, int out_size) {
    const float *x = (const float *)d_in[0];
    const float *A = (const float *)d_in[1];
    float *out = (float *)d_out;

    static int inited = 0;
    if (!inited) {
        cudaFuncSetAttribute(knn_hmma_kernel, cudaFuncAttributeMaxDynamicSharedMemorySize,
                             SMEM_KNN);
        inited = 1;
    }

    split_kernel<<<N_PTS * DIM / 4 / 256, 256>>>(x);
    sq_kernel<<<N_PTS / 8, TPB>>>(x);
    xw_kernel<<<dim3(N_PTS / BM, OUT_D / BN), TPB>>>(x, A);
    knn_hmma_kernel<<<N_PTS / 128, TPB, SMEM_KNN>>>();
    rescore_kernel<<<N_PTS, 512>>>(x, out);
}

// round 12
// speedup vs baseline: 1.7008x; 1.4870x over previous
#include <cuda_runtime.h>
#include <cuda_bf16.h>
#include <cstdint>

#define N_PTS 16384
#define DIM   512
#define OUT_D 512
#define KNN   10
#define NCAND 16

// fp32 xw tiling
#define BM 128
#define BN 128
#define KCH 32
#define TPB 256
#define LDS_ 132

#define INF_F __int_as_float(0x7f800000)

__device__ float g_sq[N_PTS];
__device__ float g_xW[N_PTS * OUT_D];
__device__ __nv_bfloat16 g_hi[(size_t)N_PTS * DIM];
__device__ int g_cand[N_PTS * NCAND];

// ---------------- helpers ----------------
__device__ __forceinline__ uint32_t smem_u32(const void *p) {
    uint32_t a;
    asm("{ .reg .u64 t; cvta.to.shared.u64 t, %1; cvt.u32.u64 %0, t; }" : "=r"(a) : "l"(p));
    return a;
}
#define SW128(o) ((o) ^ (((o) >> 3) & 0x70))

__device__ __forceinline__ void cp_async16(uint32_t dst, const void *src) {
    asm volatile("cp.async.cg.shared.global [%0], [%1], 16;" :: "r"(dst), "l"(src) : "memory");
}
#define CP_COMMIT() asm volatile("cp.async.commit_group;" ::: "memory")
#define CP_WAIT(n)  asm volatile("cp.async.wait_group %0;" :: "n"(n) : "memory")

__device__ __forceinline__ void ldsm4(uint32_t &r0, uint32_t &r1, uint32_t &r2, uint32_t &r3,
                                      uint32_t addr) {
    asm volatile("ldmatrix.sync.aligned.m8n8.x4.shared.b16 {%0,%1,%2,%3}, [%4];"
                 : "=r"(r0), "=r"(r1), "=r"(r2), "=r"(r3) : "r"(addr));
}
__device__ __forceinline__ void mma_bf16(float &c0, float &c1, float &c2, float &c3,
                                         uint32_t a0, uint32_t a1, uint32_t a2, uint32_t a3,
                                         uint32_t b0, uint32_t b1) {
    asm volatile("mma.sync.aligned.m16n8k16.row.col.f32.bf16.bf16.f32 "
                 "{%0,%1,%2,%3}, {%4,%5,%6,%7}, {%8,%9}, {%0,%1,%2,%3};"
                 : "+f"(c0), "+f"(c1), "+f"(c2), "+f"(c3)
                 : "r"(a0), "r"(a1), "r"(a2), "r"(a3), "r"(b0), "r"(b1));
}

// ---------------- fused split + row squared norms ----------------
__global__ void __launch_bounds__(256) prep_kernel(const float *__restrict__ x) {
    int row = blockIdx.x * 8 + (threadIdx.x >> 5);
    int lane = threadIdx.x & 31;
    const float4 *xr = (const float4 *)(x + (long)row * DIM);
    uint2 *hr = (uint2 *)(g_hi + (size_t)row * DIM);
    float s = 0.f;
#pragma unroll
    for (int i = 0; i < 4; i++) {
        int idx = lane + i * 32;
        float4 v = xr[idx];
        s += v.x * v.x + v.y * v.y + v.z * v.z + v.w * v.w;
        __nv_bfloat162 p0, p1;
        p0.x = __float2bfloat16_rn(v.x); p0.y = __float2bfloat16_rn(v.y);
        p1.x = __float2bfloat16_rn(v.z); p1.y = __float2bfloat16_rn(v.w);
        uint2 pk;
        pk.x = *(uint32_t *)&p0;
        pk.y = *(uint32_t *)&p1;
        hr[idx] = pk;
    }
#pragma unroll
    for (int o = 16; o; o >>= 1) s += __shfl_xor_sync(0xFFFFFFFFu, s, o);
    if (lane == 0) g_sq[row] = s;
}

// ---------------- fp32 xW = x @ A ----------------
__device__ __forceinline__ unsigned long long pack2(float x, float y) {
    unsigned long long r; asm("mov.b64 %0, {%1, %2};" : "=l"(r) : "f"(x), "f"(y)); return r;
}
__device__ __forceinline__ void unpack2(unsigned long long v, float &a, float &b) {
    asm("mov.b64 {%0, %1}, %2;" : "=f"(a), "=f"(b) : "l"(v));
}
__device__ __forceinline__ void fma2(unsigned long long &d, unsigned long long a, unsigned long long b) {
    asm("fma.rn.f32x2 %0, %1, %2, %0;" : "+l"(d) : "l"(a), "l"(b));
}
__device__ __forceinline__ void load_T(float *dst, const float *__restrict__ src, int row0, int kc, int ld) {
    int t = threadIdx.x;
#pragma unroll
    for (int i = 0; i < 4; i++) {
        int idx = t + i * TPB, r = idx >> 3, f4 = idx & 7;
        float4 v = *(const float4 *)(src + (long)(row0 + r) * ld + kc + f4 * 4);
        dst[(f4 * 4 + 0) * LDS_ + r] = v.x; dst[(f4 * 4 + 1) * LDS_ + r] = v.y;
        dst[(f4 * 4 + 2) * LDS_ + r] = v.z; dst[(f4 * 4 + 3) * LDS_ + r] = v.w;
    }
}
__device__ __forceinline__ void load_N(float *dst, const float *__restrict__ src, int kc, int col0, int ld) {
    int t = threadIdx.x;
#pragma unroll
    for (int i = 0; i < 4; i++) {
        int idx = t + i * TPB, kk = idx >> 5, c4 = idx & 31;
        float4 v = *(const float4 *)(src + (long)(kc + kk) * ld + col0 + c4 * 4);
        *(float4 *)(dst + kk * LDS_ + c4 * 4) = v;
    }
}
__global__ void __launch_bounds__(TPB) xw_kernel(const float *__restrict__ x, const float *__restrict__ A) {
    __shared__ float Xs[KCH * LDS_], Ws[KCH * LDS_];
    int m0 = blockIdx.x * BM, n0 = blockIdx.y * BN;
    int w = threadIdx.x >> 5, l = threadIdx.x & 31;
    int tx = (l & 7) | ((w & 1) << 3), ty = (l >> 3) | ((w >> 1) << 2);
    unsigned long long acc[8][4];
#pragma unroll
    for (int i = 0; i < 8; i++)
#pragma unroll
        for (int j = 0; j < 4; j++) acc[i][j] = 0ull;
    for (int kc = 0; kc < DIM; kc += KCH) {
        __syncthreads();
        load_T(Xs, x, m0, kc, DIM);
        load_N(Ws, A, kc, n0, OUT_D);
        __syncthreads();
#pragma unroll 8
        for (int kk = 0; kk < KCH; kk++) {
            const float *ar = Xs + kk * LDS_ + ty * 8;
            const float *br = Ws + kk * LDS_ + tx * 8;
            unsigned long long b2[4], a2[8];
#pragma unroll
            for (int j = 0; j < 4; j++) b2[j] = *(const unsigned long long *)(br + j * 2);
#pragma unroll
            for (int i = 0; i < 8; i++) { float av = ar[i]; a2[i] = pack2(av, av); }
#pragma unroll
            for (int i = 0; i < 8; i++)
#pragma unroll
                for (int j = 0; j < 4; j++) fma2(acc[i][j], a2[i], b2[j]);
        }
    }
#pragma unroll
    for (int i = 0; i < 8; i++) {
        int m = m0 + ty * 8 + i;
#pragma unroll
        for (int j = 0; j < 4; j++) {
            float v0, v1; unpack2(acc[i][j], v0, v1);
            int n = n0 + tx * 8 + j * 2;
            g_xW[(long)m * OUT_D + n] = v0;
            g_xW[(long)m * OUT_D + n + 1] = v1;
        }
    }
}

// ---------------- HMMA bf16 distance sweep + approx top-16 ----------------
// Byte-exact R5 kernel (3786us, tensor 23.5%). Merge scratch: mi at Ds + 4096.
// smem: A 8kblk x 128row x 128B = 131072 | B 2stg x 16KB = 32768 | Ds 128x68 f32 = 34816 | sqj 512
#define SM_A   0
#define SM_B   131072
#define SM_DS  163840
#define SM_SQJ 198656
#define SMEM_KNN 199680
#define DS_STRIDE 68

__global__ void __launch_bounds__(256, 1) knn_hmma_kernel() {
    extern __shared__ char sm[];
    uint32_t sb = smem_u32(sm);
    float *Ds = (float *)(sm + SM_DS);
    float *sqj_s = (float *)(sm + SM_SQJ);

    int tid = threadIdx.x;
    int lane = tid & 31, w = tid >> 5;
    int wm = w >> 2, wn = w & 3;          // warp grid 2(M) x 4(N)
    int hme = wn >> 1;                    // which 64-col half this warp's output is in
    int r0 = blockIdx.x * 128;

    int lrow = lane & 15;
    int lkp  = (lane >> 4) * 8;

    // ---- preload full A tile (8 k-blocks) + B chunk q=0 ----
    {
        const __nv_bfloat16 *Ab = g_hi + (size_t)r0 * DIM;
#pragma unroll
        for (int u = 0; u < 32; u++) {
            int g = tid + u * 256;
            int kblk = g >> 10, rem = g & 1023;
            int row = rem >> 3, k8 = (rem & 7) * 8;
            uint32_t dst = sb + SM_A + kblk * 16384 + SW128(row * 128 + k8 * 2);
            cp_async16(dst, Ab + (size_t)row * DIM + kblk * 64 + k8);
        }
        CP_COMMIT();
#pragma unroll
        for (int u = 0; u < 4; u++) {
            int g = tid + u * 256;
            int row = g >> 3, k8 = (g & 7) * 8;
            uint32_t dst = sb + SM_B + SW128(row * 128 + k8 * 2);
            cp_async16(dst, g_hi + (size_t)row * DIM + k8);   // j=0, kb=0
        }
        CP_COMMIT();
    }

    float bd[NCAND];
    int bi[NCAND];
#pragma unroll
    for (int k = 0; k < NCAND; k++) { bd[k] = INF_F; bi[k] = -1; }
    float th = INF_F;

    for (int j = 0; j < 128; j++) {
        float acc[4][4][4];
#pragma unroll
        for (int a = 0; a < 4; a++)
#pragma unroll
            for (int b = 0; b < 4; b++)
#pragma unroll
                for (int c = 0; c < 4; c++) acc[a][b][c] = 0.f;

        for (int kb = 0; kb < 8; kb++) {
            int q = j * 8 + kb;
            int stage = q & 1;

            // complete chunk q, barrier, THEN overwrite the other stage.
            CP_WAIT(0);
            __syncthreads();
            if (kb == 0 && tid < 128) sqj_s[tid] = g_sq[j * 128 + tid];

            if (q + 1 < 1024) {
                int qn = q + 1;
                int jn = qn >> 3, kbn = qn & 7, sn = stage ^ 1;
#pragma unroll
                for (int u = 0; u < 4; u++) {
                    int g = tid + u * 256;
                    int row = g >> 3, k8 = (g & 7) * 8;
                    uint32_t dst = sb + SM_B + sn * 16384 + SW128(row * 128 + k8 * 2);
                    cp_async16(dst, g_hi + (size_t)(jn * 128 + row) * DIM + kbn * 64 + k8);
                }
                CP_COMMIT();
            }

            uint32_t Ab = sb + SM_A + kb * 16384;
            uint32_t Bb = sb + SM_B + stage * 16384;
#pragma unroll
            for (int ks = 0; ks < 4; ks++) {
                int koff = ks * 16 + lkp;
                uint32_t b0, b1, b2, b3, b4, b5, b6, b7;
                {
                    int n = wn * 32 + lrow;
                    ldsm4(b0, b1, b2, b3, Bb + SW128(n * 128 + koff * 2));
                    ldsm4(b4, b5, b6, b7, Bb + SW128((n + 16) * 128 + koff * 2));
                }
#pragma unroll
                for (int mb = 0; mb < 4; mb++) {
                    uint32_t a0, a1, a2, a3;
                    int m = wm * 64 + mb * 16 + lrow;
                    ldsm4(a0, a1, a2, a3, Ab + SW128(m * 128 + koff * 2));
                    mma_bf16(acc[mb][0][0], acc[mb][0][1], acc[mb][0][2], acc[mb][0][3],
                             a0, a1, a2, a3, b0, b2);
                    mma_bf16(acc[mb][1][0], acc[mb][1][1], acc[mb][1][2], acc[mb][1][3],
                             a0, a1, a2, a3, b1, b3);
                    mma_bf16(acc[mb][2][0], acc[mb][2][1], acc[mb][2][2], acc[mb][2][3],
                             a0, a1, a2, a3, b4, b6);
                    mma_bf16(acc[mb][3][0], acc[mb][3][1], acc[mb][3][2], acc[mb][3][3],
                             a0, a1, a2, a3, b5, b7);
                }
            }
        }

        // ---- epilogue: two 64-col halves through Ds ----
#pragma unroll
        for (int half = 0; half < 2; half++) {
            __syncthreads();
            if (hme == half) {
#pragma unroll
                for (int mb = 0; mb < 4; mb++) {
                    int r1 = wm * 64 + mb * 16 + (lane >> 2);
#pragma unroll
                    for (int nb = 0; nb < 4; nb++) {
                        int cb = (wn & 1) * 32 + nb * 8 + (lane & 3) * 2;
                        float2 v0, v1;
                        v0.x = acc[mb][nb][0]; v0.y = acc[mb][nb][1];
                        v1.x = acc[mb][nb][2]; v1.y = acc[mb][nb][3];
                        *(float2 *)(Ds + r1 * DS_STRIDE + cb) = v0;
                        *(float2 *)(Ds + (r1 + 8) * DS_STRIDE + cb) = v1;
                    }
                }
            }
            __syncthreads();
            {
                int row = tid & 127, seg = tid >> 7;
                int gm = r0 + row;
                const float *dr = Ds + row * DS_STRIDE + seg * 32;
                int ctile = half * 64 + seg * 32;
                int jb = j * 128 + ctile;
#pragma unroll 4
                for (int c4 = 0; c4 < 8; c4++) {
                    float4 v = *(const float4 *)(dr + c4 * 4);
                    const float *sq4 = sqj_s + ctile + c4 * 4;
                    int cb = jb + c4 * 4;
                    float s0 = sq4[0] - 2.0f * v.x;
                    float s1 = sq4[1] - 2.0f * v.y;
                    float s2 = sq4[2] - 2.0f * v.z;
                    float s3 = sq4[3] - 2.0f * v.w;
                    if (s0 < th && cb + 0 != gm) {
                        int p = NCAND - 1;
                        while (p > 0 && bd[p - 1] > s0) { bd[p] = bd[p - 1]; bi[p] = bi[p - 1]; p--; }
                        bd[p] = s0; bi[p] = cb + 0; th = bd[NCAND - 1];
                    }
                    if (s1 < th && cb + 1 != gm) {
                        int p = NCAND - 1;
                        while (p > 0 && bd[p - 1] > s1) { bd[p] = bd[p - 1]; bi[p] = bi[p - 1]; p--; }
                        bd[p] = s1; bi[p] = cb + 1; th = bd[NCAND - 1];
                    }
                    if (s2 < th && cb + 2 != gm) {
                        int p = NCAND - 1;
                        while (p > 0 && bd[p - 1] > s2) { bd[p] = bd[p - 1]; bi[p] = bi[p - 1]; p--; }
                        bd[p] = s2; bi[p] = cb + 2; th = bd[NCAND - 1];
                    }
                    if (s3 < th && cb + 3 != gm) {
                        int p = NCAND - 1;
                        while (p > 0 && bd[p - 1] > s3) { bd[p] = bd[p - 1]; bi[p] = bi[p - 1]; p--; }
                        bd[p] = s3; bi[p] = cb + 3; th = bd[NCAND - 1];
                    }
                }
            }
        }
    }

    // ---- merge the two per-row half-lists, emit top-16 candidates ----
    __syncthreads();
    float *md = Ds;                         // 256*16 floats = Ds[0..4096)
    int *mi = (int *)(Ds + 4096);           // 256*16 ints   = Ds[4096..8192)
#pragma unroll
    for (int k = 0; k < NCAND; k++) {
        md[tid * NCAND + k] = bd[k];
        mi[tid * NCAND + k] = bi[k];
    }
    __syncthreads();
    if (tid < 128) {
        const float *da = md + tid * NCAND;
        const int *ia = mi + tid * NCAND;
        const float *db = md + (tid + 128) * NCAND;
        const int *ib = mi + (tid + 128) * NCAND;
        int pa = 0, pb = 0;
#pragma unroll
        for (int k = 0; k < NCAND; k++) {
            float va = da[pa], vb = db[pb];
            bool takeA = (va < vb) || (va == vb && ia[pa] < ib[pb]);
            int sel = takeA ? ia[pa] : ib[pb];
            if (takeA) pa++; else pb++;
            g_cand[(r0 + tid) * NCAND + k] = sel;
        }
    }
}

// ---------------- exact fp32 rescore + gather-sum ----------------
__global__ void __launch_bounds__(512) rescore_kernel(const float *__restrict__ x,
                                                      float *__restrict__ out) {
    __shared__ float xr[512];
    __shared__ float cd[NCAND];
    __shared__ int ci[NCAND];
    __shared__ int sel[KNN];
    int row = blockIdx.x;
    int tid = threadIdx.x;
    int w = tid >> 5, lane = tid & 31;
    xr[tid] = x[(long)row * DIM + tid];
    if (tid < NCAND) {
        int c = g_cand[row * NCAND + tid];
        if (c < 0 || c >= N_PTS) c = -1;    // defensive clamp: never deref garbage
        ci[tid] = c;
    }
    __syncthreads();
    {
        int c = ci[w];
        float s = 0.f;
        if (c >= 0) {
            const float *xc = x + (long)c * DIM;
#pragma unroll
            for (int t = 0; t < 16; t++) {
                int e = lane + 32 * t;
                s += xr[e] * xc[e];
            }
        }
#pragma unroll
        for (int o = 16; o; o >>= 1) s += __shfl_xor_sync(0xFFFFFFFFu, s, o);
        if (lane == 0) cd[w] = (c >= 0) ? (g_sq[row] + g_sq[c] - 2.0f * s) : INF_F;
    }
    __syncthreads();
    if (tid == 0) {
        unsigned used = 0;
        for (int k = 0; k < KNN; k++) {
            float best = INF_F; int bidx = 0x7FFFFFFF, bw = 0;
            for (int q = 0; q < NCAND; q++) {
                if (used & (1u << q)) continue;
                float d = cd[q]; int id = ci[q];
                if (d < best || (d == best && id < bidx)) { best = d; bidx = id; bw = q; }
            }
            used |= 1u << bw;
            sel[k] = bidx;
        }
    }
    __syncthreads();
    float s = 0.f;
#pragma unroll
    for (int k = 0; k < KNN; k++) s += g_xW[(long)sel[k] * OUT_D + tid];
    out[(long)row * OUT_D + tid] = s;
}

// ---------------- launcher ----------------
extern "C" void kernel_launch(void *const *d_in, const int *in_sizes, int n_in,
                              void *d_out, int out_size) {
    const float *x = (const float *)d_in[0];
    const float *A = (const float *)d_in[1];
    float *out = (float *)d_out;

    static int inited = 0;
    if (!inited) {
        cudaFuncSetAttribute(knn_hmma_kernel, cudaFuncAttributeMaxDynamicSharedMemorySize,
                             SMEM_KNN);
        inited = 1;
    }

    prep_kernel<<<N_PTS / 8, 256>>>(x);
    xw_kernel<<<dim3(N_PTS / BM, OUT_D / BN), TPB>>>(x, A);
    knn_hmma_kernel<<<N_PTS / 128, TPB, SMEM_KNN>>>();
    rescore_kernel<<<N_PTS, 512>>>(x, out);
}

// round 14
// speedup vs baseline: 1.7016x; 1.0005x over previous
#include <cuda_runtime.h>
#include <cuda_bf16.h>
#include <cstdint>

#define N_PTS 16384
#define DIM   512
#define OUT_D 512
#define KNN   10
#define NCAND 16

// fp32 xw tiling
#define BM 128
#define BN 128
#define KCH 32
#define TPB 256
#define LDS_ 132

#define INF_F __int_as_float(0x7f800000)

__device__ float g_sq[N_PTS];
__device__ float g_xW[N_PTS * OUT_D];
__device__ __nv_bfloat16 g_hi[(size_t)N_PTS * DIM];
__device__ int g_cand[N_PTS * NCAND];

// ---------------- helpers ----------------
__device__ __forceinline__ uint32_t smem_u32(const void *p) {
    uint32_t a;
    asm("{ .reg .u64 t; cvta.to.shared.u64 t, %1; cvt.u32.u64 %0, t; }" : "=r"(a) : "l"(p));
    return a;
}
#define SW128(o) ((o) ^ (((o) >> 3) & 0x70))

__device__ __forceinline__ void cp_async16(uint32_t dst, const void *src) {
    asm volatile("cp.async.cg.shared.global [%0], [%1], 16;" :: "r"(dst), "l"(src) : "memory");
}
#define CP_COMMIT() asm volatile("cp.async.commit_group;" ::: "memory")
#define CP_WAIT(n)  asm volatile("cp.async.wait_group %0;" :: "n"(n) : "memory")

__device__ __forceinline__ void ldsm4(uint32_t &r0, uint32_t &r1, uint32_t &r2, uint32_t &r3,
                                      uint32_t addr) {
    asm volatile("ldmatrix.sync.aligned.m8n8.x4.shared.b16 {%0,%1,%2,%3}, [%4];"
                 : "=r"(r0), "=r"(r1), "=r"(r2), "=r"(r3) : "r"(addr));
}
__device__ __forceinline__ void mma_bf16(float &c0, float &c1, float &c2, float &c3,
                                         uint32_t a0, uint32_t a1, uint32_t a2, uint32_t a3,
                                         uint32_t b0, uint32_t b1) {
    asm volatile("mma.sync.aligned.m16n8k16.row.col.f32.bf16.bf16.f32 "
                 "{%0,%1,%2,%3}, {%4,%5,%6,%7}, {%8,%9}, {%0,%1,%2,%3};"
                 : "+f"(c0), "+f"(c1), "+f"(c2), "+f"(c3)
                 : "r"(a0), "r"(a1), "r"(a2), "r"(a3), "r"(b0), "r"(b1));
}

// ---------------- fused split + row squared norms ----------------
__global__ void __launch_bounds__(256) prep_kernel(const float *__restrict__ x) {
    int row = blockIdx.x * 8 + (threadIdx.x >> 5);
    int lane = threadIdx.x & 31;
    const float4 *xr = (const float4 *)(x + (long)row * DIM);
    uint2 *hr = (uint2 *)(g_hi + (size_t)row * DIM);
    float s = 0.f;
#pragma unroll
    for (int i = 0; i < 4; i++) {
        int idx = lane + i * 32;
        float4 v = xr[idx];
        s += v.x * v.x + v.y * v.y + v.z * v.z + v.w * v.w;
        __nv_bfloat162 p0, p1;
        p0.x = __float2bfloat16_rn(v.x); p0.y = __float2bfloat16_rn(v.y);
        p1.x = __float2bfloat16_rn(v.z); p1.y = __float2bfloat16_rn(v.w);
        uint2 pk;
        pk.x = *(uint32_t *)&p0;
        pk.y = *(uint32_t *)&p1;
        hr[idx] = pk;
    }
#pragma unroll
    for (int o = 16; o; o >>= 1) s += __shfl_xor_sync(0xFFFFFFFFu, s, o);
    if (lane == 0) g_sq[row] = s;
}

// ---------------- fp32 xW = x @ A ----------------
__device__ __forceinline__ unsigned long long pack2(float x, float y) {
    unsigned long long r; asm("mov.b64 %0, {%1, %2};" : "=l"(r) : "f"(x), "f"(y)); return r;
}
__device__ __forceinline__ void unpack2(unsigned long long v, float &a, float &b) {
    asm("mov.b64 {%0, %1}, %2;" : "=f"(a), "=f"(b) : "l"(v));
}
__device__ __forceinline__ void fma2(unsigned long long &d, unsigned long long a, unsigned long long b) {
    asm("fma.rn.f32x2 %0, %1, %2, %0;" : "+l"(d) : "l"(a), "l"(b));
}
__device__ __forceinline__ void load_T(float *dst, const float *__restrict__ src, int row0, int kc, int ld) {
    int t = threadIdx.x;
#pragma unroll
    for (int i = 0; i < 4; i++) {
        int idx = t + i * TPB, r = idx >> 3, f4 = idx & 7;
        float4 v = *(const float4 *)(src + (long)(row0 + r) * ld + kc + f4 * 4);
        dst[(f4 * 4 + 0) * LDS_ + r] = v.x; dst[(f4 * 4 + 1) * LDS_ + r] = v.y;
        dst[(f4 * 4 + 2) * LDS_ + r] = v.z; dst[(f4 * 4 + 3) * LDS_ + r] = v.w;
    }
}
__device__ __forceinline__ void load_N(float *dst, const float *__restrict__ src, int kc, int col0, int ld) {
    int t = threadIdx.x;
#pragma unroll
    for (int i = 0; i < 4; i++) {
        int idx = t + i * TPB, kk = idx >> 5, c4 = idx & 31;
        float4 v = *(const float4 *)(src + (long)(kc + kk) * ld + col0 + c4 * 4);
        *(float4 *)(dst + kk * LDS_ + c4 * 4) = v;
    }
}
__global__ void __launch_bounds__(TPB) xw_kernel(const float *__restrict__ x, const float *__restrict__ A) {
    __shared__ float Xs[KCH * LDS_], Ws[KCH * LDS_];
    int m0 = blockIdx.x * BM, n0 = blockIdx.y * BN;
    int w = threadIdx.x >> 5, l = threadIdx.x & 31;
    int tx = (l & 7) | ((w & 1) << 3), ty = (l >> 3) | ((w >> 1) << 2);
    unsigned long long acc[8][4];
#pragma unroll
    for (int i = 0; i < 8; i++)
#pragma unroll
        for (int j = 0; j < 4; j++) acc[i][j] = 0ull;
    for (int kc = 0; kc < DIM; kc += KCH) {
        __syncthreads();
        load_T(Xs, x, m0, kc, DIM);
        load_N(Ws, A, kc, n0, OUT_D);
        __syncthreads();
#pragma unroll 8
        for (int kk = 0; kk < KCH; kk++) {
            const float *ar = Xs + kk * LDS_ + ty * 8;
            const float *br = Ws + kk * LDS_ + tx * 8;
            unsigned long long b2[4], a2[8];
#pragma unroll
            for (int j = 0; j < 4; j++) b2[j] = *(const unsigned long long *)(br + j * 2);
#pragma unroll
            for (int i = 0; i < 8; i++) { float av = ar[i]; a2[i] = pack2(av, av); }
#pragma unroll
            for (int i = 0; i < 8; i++)
#pragma unroll
                for (int j = 0; j < 4; j++) fma2(acc[i][j], a2[i], b2[j]);
        }
    }
#pragma unroll
    for (int i = 0; i < 8; i++) {
        int m = m0 + ty * 8 + i;
#pragma unroll
        for (int j = 0; j < 4; j++) {
            float v0, v1; unpack2(acc[i][j], v0, v1);
            int n = n0 + tx * 8 + j * 2;
            g_xW[(long)m * OUT_D + n] = v0;
            g_xW[(long)m * OUT_D + n + 1] = v1;
        }
    }
}

// ---------------- HMMA bf16 distance sweep + approx top-16 ----------------
// Byte-exact R5/R12 kernel (3786/3818us, tensor 23.5%). FROZEN.
// smem: A 8kblk x 128row x 128B = 131072 | B 2stg x 16KB = 32768 | Ds 128x68 f32 = 34816 | sqj 512
#define SM_A   0
#define SM_B   131072
#define SM_DS  163840
#define SM_SQJ 198656
#define SMEM_KNN 199680
#define DS_STRIDE 68

__global__ void __launch_bounds__(256, 1) knn_hmma_kernel() {
    extern __shared__ char sm[];
    uint32_t sb = smem_u32(sm);
    float *Ds = (float *)(sm + SM_DS);
    float *sqj_s = (float *)(sm + SM_SQJ);

    int tid = threadIdx.x;
    int lane = tid & 31, w = tid >> 5;
    int wm = w >> 2, wn = w & 3;          // warp grid 2(M) x 4(N)
    int hme = wn >> 1;                    // which 64-col half this warp's output is in
    int r0 = blockIdx.x * 128;

    int lrow = lane & 15;
    int lkp  = (lane >> 4) * 8;

    // ---- preload full A tile (8 k-blocks) + B chunk q=0 ----
    {
        const __nv_bfloat16 *Ab = g_hi + (size_t)r0 * DIM;
#pragma unroll
        for (int u = 0; u < 32; u++) {
            int g = tid + u * 256;
            int kblk = g >> 10, rem = g & 1023;
            int row = rem >> 3, k8 = (rem & 7) * 8;
            uint32_t dst = sb + SM_A + kblk * 16384 + SW128(row * 128 + k8 * 2);
            cp_async16(dst, Ab + (size_t)row * DIM + kblk * 64 + k8);
        }
        CP_COMMIT();
#pragma unroll
        for (int u = 0; u < 4; u++) {
            int g = tid + u * 256;
            int row = g >> 3, k8 = (g & 7) * 8;
            uint32_t dst = sb + SM_B + SW128(row * 128 + k8 * 2);
            cp_async16(dst, g_hi + (size_t)row * DIM + k8);   // j=0, kb=0
        }
        CP_COMMIT();
    }

    float bd[NCAND];
    int bi[NCAND];
#pragma unroll
    for (int k = 0; k < NCAND; k++) { bd[k] = INF_F; bi[k] = -1; }
    float th = INF_F;

    for (int j = 0; j < 128; j++) {
        float acc[4][4][4];
#pragma unroll
        for (int a = 0; a < 4; a++)
#pragma unroll
            for (int b = 0; b < 4; b++)
#pragma unroll
                for (int c = 0; c < 4; c++) acc[a][b][c] = 0.f;

        for (int kb = 0; kb < 8; kb++) {
            int q = j * 8 + kb;
            int stage = q & 1;

            // complete chunk q, barrier, THEN overwrite the other stage.
            CP_WAIT(0);
            __syncthreads();
            if (kb == 0 && tid < 128) sqj_s[tid] = g_sq[j * 128 + tid];

            if (q + 1 < 1024) {
                int qn = q + 1;
                int jn = qn >> 3, kbn = qn & 7, sn = stage ^ 1;
#pragma unroll
                for (int u = 0; u < 4; u++) {
                    int g = tid + u * 256;
                    int row = g >> 3, k8 = (g & 7) * 8;
                    uint32_t dst = sb + SM_B + sn * 16384 + SW128(row * 128 + k8 * 2);
                    cp_async16(dst, g_hi + (size_t)(jn * 128 + row) * DIM + kbn * 64 + k8);
                }
                CP_COMMIT();
            }

            uint32_t Ab = sb + SM_A + kb * 16384;
            uint32_t Bb = sb + SM_B + stage * 16384;
#pragma unroll
            for (int ks = 0; ks < 4; ks++) {
                int koff = ks * 16 + lkp;
                uint32_t b0, b1, b2, b3, b4, b5, b6, b7;
                {
                    int n = wn * 32 + lrow;
                    ldsm4(b0, b1, b2, b3, Bb + SW128(n * 128 + koff * 2));
                    ldsm4(b4, b5, b6, b7, Bb + SW128((n + 16) * 128 + koff * 2));
                }
#pragma unroll
                for (int mb = 0; mb < 4; mb++) {
                    uint32_t a0, a1, a2, a3;
                    int m = wm * 64 + mb * 16 + lrow;
                    ldsm4(a0, a1, a2, a3, Ab + SW128(m * 128 + koff * 2));
                    mma_bf16(acc[mb][0][0], acc[mb][0][1], acc[mb][0][2], acc[mb][0][3],
                             a0, a1, a2, a3, b0, b2);
                    mma_bf16(acc[mb][1][0], acc[mb][1][1], acc[mb][1][2], acc[mb][1][3],
                             a0, a1, a2, a3, b1, b3);
                    mma_bf16(acc[mb][2][0], acc[mb][2][1], acc[mb][2][2], acc[mb][2][3],
                             a0, a1, a2, a3, b4, b6);
                    mma_bf16(acc[mb][3][0], acc[mb][3][1], acc[mb][3][2], acc[mb][3][3],
                             a0, a1, a2, a3, b5, b7);
                }
            }
        }

        // ---- epilogue: two 64-col halves through Ds ----
#pragma unroll
        for (int half = 0; half < 2; half++) {
            __syncthreads();
            if (hme == half) {
#pragma unroll
                for (int mb = 0; mb < 4; mb++) {
                    int r1 = wm * 64 + mb * 16 + (lane >> 2);
#pragma unroll
                    for (int nb = 0; nb < 4; nb++) {
                        int cb = (wn & 1) * 32 + nb * 8 + (lane & 3) * 2;
                        float2 v0, v1;
                        v0.x = acc[mb][nb][0]; v0.y = acc[mb][nb][1];
                        v1.x = acc[mb][nb][2]; v1.y = acc[mb][nb][3];
                        *(float2 *)(Ds + r1 * DS_STRIDE + cb) = v0;
                        *(float2 *)(Ds + (r1 + 8) * DS_STRIDE + cb) = v1;
                    }
                }
            }
            __syncthreads();
            {
                int row = tid & 127, seg = tid >> 7;
                int gm = r0 + row;
                const float *dr = Ds + row * DS_STRIDE + seg * 32;
                int ctile = half * 64 + seg * 32;
                int jb = j * 128 + ctile;
#pragma unroll 4
                for (int c4 = 0; c4 < 8; c4++) {
                    float4 v = *(const float4 *)(dr + c4 * 4);
                    const float *sq4 = sqj_s + ctile + c4 * 4;
                    int cb = jb + c4 * 4;
                    float s0 = sq4[0] - 2.0f * v.x;
                    float s1 = sq4[1] - 2.0f * v.y;
                    float s2 = sq4[2] - 2.0f * v.z;
                    float s3 = sq4[3] - 2.0f * v.w;
                    if (s0 < th && cb + 0 != gm) {
                        int p = NCAND - 1;
                        while (p > 0 && bd[p - 1] > s0) { bd[p] = bd[p - 1]; bi[p] = bi[p - 1]; p--; }
                        bd[p] = s0; bi[p] = cb + 0; th = bd[NCAND - 1];
                    }
                    if (s1 < th && cb + 1 != gm) {
                        int p = NCAND - 1;
                        while (p > 0 && bd[p - 1] > s1) { bd[p] = bd[p - 1]; bi[p] = bi[p - 1]; p--; }
                        bd[p] = s1; bi[p] = cb + 1; th = bd[NCAND - 1];
                    }
                    if (s2 < th && cb + 2 != gm) {
                        int p = NCAND - 1;
                        while (p > 0 && bd[p - 1] > s2) { bd[p] = bd[p - 1]; bi[p] = bi[p - 1]; p--; }
                        bd[p] = s2; bi[p] = cb + 2; th = bd[NCAND - 1];
                    }
                    if (s3 < th && cb + 3 != gm) {
                        int p = NCAND - 1;
                        while (p > 0 && bd[p - 1] > s3) { bd[p] = bd[p - 1]; bi[p] = bi[p - 1]; p--; }
                        bd[p] = s3; bi[p] = cb + 3; th = bd[NCAND - 1];
                    }
                }
            }
        }
    }

    // ---- merge the two per-row half-lists, emit top-16 candidates ----
    __syncthreads();
    float *md = Ds;                         // 256*16 floats = Ds[0..4096)
    int *mi = (int *)(Ds + 4096);           // 256*16 ints   = Ds[4096..8192)
#pragma unroll
    for (int k = 0; k < NCAND; k++) {
        md[tid * NCAND + k] = bd[k];
        mi[tid * NCAND + k] = bi[k];
    }
    __syncthreads();
    if (tid < 128) {
        const float *da = md + tid * NCAND;
        const int *ia = mi + tid * NCAND;
        const float *db = md + (tid + 128) * NCAND;
        const int *ib = mi + (tid + 128) * NCAND;
        int pa = 0, pb = 0;
#pragma unroll
        for (int k = 0; k < NCAND; k++) {
            float va = da[pa], vb = db[pb];
            bool takeA = (va < vb) || (va == vb && ia[pa] < ib[pb]);
            int sel = takeA ? ia[pa] : ib[pb];
            if (takeA) pa++; else pb++;
            g_cand[(r0 + tid) * NCAND + k] = sel;
        }
    }
}

// ---------------- exact fp32 rescore + gather-sum ----------------
// Dot product: byte-exact R12 ordering (selection is order-sensitive -> FROZEN).
// Gather-sum: float4 vectorized (identical k-order per element -> bitwise same).
__global__ void __launch_bounds__(512) rescore_kernel(const float *__restrict__ x,
                                                      float *__restrict__ out) {
    __shared__ float xr[512];
    __shared__ float cd[NCAND];
    __shared__ int ci[NCAND];
    __shared__ int sel[KNN];
    int row = blockIdx.x;
    int tid = threadIdx.x;
    int w = tid >> 5, lane = tid & 31;
    xr[tid] = x[(long)row * DIM + tid];
    if (tid < NCAND) {
        int c = g_cand[row * NCAND + tid];
        if (c < 0 || c >= N_PTS) c = -1;    // defensive clamp: never deref garbage
        ci[tid] = c;
    }
    __syncthreads();
    {
        int c = ci[w];
        float s = 0.f;
        if (c >= 0) {
            const float *xc = x + (long)c * DIM;
#pragma unroll
            for (int t = 0; t < 16; t++) {
                int e = lane + 32 * t;
                s += xr[e] * xc[e];
            }
        }
#pragma unroll
        for (int o = 16; o; o >>= 1) s += __shfl_xor_sync(0xFFFFFFFFu, s, o);
        if (lane == 0) cd[w] = (c >= 0) ? (g_sq[row] + g_sq[c] - 2.0f * s) : INF_F;
    }
    __syncthreads();
    if (tid == 0) {
        unsigned used = 0;
        for (int k = 0; k < KNN; k++) {
            float best = INF_F; int bidx = 0x7FFFFFFF, bw = 0;
            for (int q = 0; q < NCAND; q++) {
                if (used & (1u << q)) continue;
                float d = cd[q]; int id = ci[q];
                if (d < best || (d == best && id < bidx)) { best = d; bidx = id; bw = q; }
            }
            used |= 1u << bw;
            sel[k] = bidx;
        }
    }
    __syncthreads();
    // gather-sum: 128 threads x float4 (same per-element k-order as scalar version)
    if (tid < 128) {
        float4 s = make_float4(0.f, 0.f, 0.f, 0.f);
#pragma unroll
        for (int k = 0; k < KNN; k++) {
            float4 v = ((const float4 *)(g_xW + (long)sel[k] * OUT_D))[tid];
            s.x += v.x; s.y += v.y; s.z += v.z; s.w += v.w;
        }
        ((float4 *)(out + (long)row * OUT_D))[tid] = s;
    }
}

// ---------------- launcher ----------------
extern "C" void kernel_launch(void *const *d_in, const int *in_sizes, int n_in,
                              void *d_out, int out_size) {
    const float *x = (const float *)d_in[0];
    const float *A = (const float *)d_in[1];
    float *out = (float *)d_out;

    static int inited = 0;
    if (!inited) {
        cudaFuncSetAttribute(knn_hmma_kernel, cudaFuncAttributeMaxDynamicSharedMemorySize,
                             SMEM_KNN);
        inited = 1;
    }

    prep_kernel<<<N_PTS / 8, 256>>>(x);
    xw_kernel<<<dim3(N_PTS / BM, OUT_D / BN), TPB>>>(x, A);
    knn_hmma_kernel<<<N_PTS / 128, TPB, SMEM_KNN>>>();
    rescore_kernel<<<N_PTS, 512>>>(x, out);
}

// round 15
// speedup vs baseline: 1.7219x; 1.0119x over previous
#include <cuda_runtime.h>
#include <cuda_bf16.h>
#include <cstdint>

#define N_PTS 16384
#define DIM   512
#define OUT_D 512
#define KNN   10
#define NCAND 16

// fp32 xw tiling
#define BM 128
#define BN 128
#define KCH 32
#define TPB 256
#define LDS_ 132

#define INF_F __int_as_float(0x7f800000)

__device__ float g_sq[N_PTS];
__device__ float g_xW[N_PTS * OUT_D];
__device__ __nv_bfloat16 g_hi[(size_t)N_PTS * DIM];
__device__ int g_cand[N_PTS * NCAND];

// ---------------- helpers ----------------
__device__ __forceinline__ uint32_t smem_u32(const void *p) {
    uint32_t a;
    asm("{ .reg .u64 t; cvta.to.shared.u64 t, %1; cvt.u32.u64 %0, t; }" : "=r"(a) : "l"(p));
    return a;
}
#define SW128(o) ((o) ^ (((o) >> 3) & 0x70))

__device__ __forceinline__ void cp_async16(uint32_t dst, const void *src) {
    asm volatile("cp.async.cg.shared.global [%0], [%1], 16;" :: "r"(dst), "l"(src) : "memory");
}
#define CP_COMMIT() asm volatile("cp.async.commit_group;" ::: "memory")
#define CP_WAIT(n)  asm volatile("cp.async.wait_group %0;" :: "n"(n) : "memory")

__device__ __forceinline__ void ldsm4(uint32_t &r0, uint32_t &r1, uint32_t &r2, uint32_t &r3,
                                      uint32_t addr) {
    asm volatile("ldmatrix.sync.aligned.m8n8.x4.shared.b16 {%0,%1,%2,%3}, [%4];"
                 : "=r"(r0), "=r"(r1), "=r"(r2), "=r"(r3) : "r"(addr));
}
__device__ __forceinline__ void mma_bf16(float &c0, float &c1, float &c2, float &c3,
                                         uint32_t a0, uint32_t a1, uint32_t a2, uint32_t a3,
                                         uint32_t b0, uint32_t b1) {
    asm volatile("mma.sync.aligned.m16n8k16.row.col.f32.bf16.bf16.f32 "
                 "{%0,%1,%2,%3}, {%4,%5,%6,%7}, {%8,%9}, {%0,%1,%2,%3};"
                 : "+f"(c0), "+f"(c1), "+f"(c2), "+f"(c3)
                 : "r"(a0), "r"(a1), "r"(a2), "r"(a3), "r"(b0), "r"(b1));
}

// ---------------- fused split + row squared norms ----------------
__global__ void __launch_bounds__(256) prep_kernel(const float *__restrict__ x) {
    int row = blockIdx.x * 8 + (threadIdx.x >> 5);
    int lane = threadIdx.x & 31;
    const float4 *xr = (const float4 *)(x + (long)row * DIM);
    uint2 *hr = (uint2 *)(g_hi + (size_t)row * DIM);
    float s = 0.f;
#pragma unroll
    for (int i = 0; i < 4; i++) {
        int idx = lane + i * 32;
        float4 v = xr[idx];
        s += v.x * v.x + v.y * v.y + v.z * v.z + v.w * v.w;
        __nv_bfloat162 p0, p1;
        p0.x = __float2bfloat16_rn(v.x); p0.y = __float2bfloat16_rn(v.y);
        p1.x = __float2bfloat16_rn(v.z); p1.y = __float2bfloat16_rn(v.w);
        uint2 pk;
        pk.x = *(uint32_t *)&p0;
        pk.y = *(uint32_t *)&p1;
        hr[idx] = pk;
    }
#pragma unroll
    for (int o = 16; o; o >>= 1) s += __shfl_xor_sync(0xFFFFFFFFu, s, o);
    if (lane == 0) g_sq[row] = s;
}

// ---------------- fp32 xW = x @ A ----------------
__device__ __forceinline__ unsigned long long pack2(float x, float y) {
    unsigned long long r; asm("mov.b64 %0, {%1, %2};" : "=l"(r) : "f"(x), "f"(y)); return r;
}
__device__ __forceinline__ void unpack2(unsigned long long v, float &a, float &b) {
    asm("mov.b64 {%0, %1}, %2;" : "=f"(a), "=f"(b) : "l"(v));
}
__device__ __forceinline__ void fma2(unsigned long long &d, unsigned long long a, unsigned long long b) {
    asm("fma.rn.f32x2 %0, %1, %2, %0;" : "+l"(d) : "l"(a), "l"(b));
}
__device__ __forceinline__ void load_T(float *dst, const float *__restrict__ src, int row0, int kc, int ld) {
    int t = threadIdx.x;
#pragma unroll
    for (int i = 0; i < 4; i++) {
        int idx = t + i * TPB, r = idx >> 3, f4 = idx & 7;
        float4 v = *(const float4 *)(src + (long)(row0 + r) * ld + kc + f4 * 4);
        dst[(f4 * 4 + 0) * LDS_ + r] = v.x; dst[(f4 * 4 + 1) * LDS_ + r] = v.y;
        dst[(f4 * 4 + 2) * LDS_ + r] = v.z; dst[(f4 * 4 + 3) * LDS_ + r] = v.w;
    }
}
__device__ __forceinline__ void load_N(float *dst, const float *__restrict__ src, int kc, int col0, int ld) {
    int t = threadIdx.x;
#pragma unroll
    for (int i = 0; i < 4; i++) {
        int idx = t + i * TPB, kk = idx >> 5, c4 = idx & 31;
        float4 v = *(const float4 *)(src + (long)(kc + kk) * ld + col0 + c4 * 4);
        *(float4 *)(dst + kk * LDS_ + c4 * 4) = v;
    }
}
__global__ void __launch_bounds__(TPB) xw_kernel(const float *__restrict__ x, const float *__restrict__ A) {
    __shared__ float Xs[KCH * LDS_], Ws[KCH * LDS_];
    int m0 = blockIdx.x * BM, n0 = blockIdx.y * BN;
    int w = threadIdx.x >> 5, l = threadIdx.x & 31;
    int tx = (l & 7) | ((w & 1) << 3), ty = (l >> 3) | ((w >> 1) << 2);
    unsigned long long acc[8][4];
#pragma unroll
    for (int i = 0; i < 8; i++)
#pragma unroll
        for (int j = 0; j < 4; j++) acc[i][j] = 0ull;
    for (int kc = 0; kc < DIM; kc += KCH) {
        __syncthreads();
        load_T(Xs, x, m0, kc, DIM);
        load_N(Ws, A, kc, n0, OUT_D);
        __syncthreads();
#pragma unroll 8
        for (int kk = 0; kk < KCH; kk++) {
            const float *ar = Xs + kk * LDS_ + ty * 8;
            const float *br = Ws + kk * LDS_ + tx * 8;
            unsigned long long b2[4], a2[8];
#pragma unroll
            for (int j = 0; j < 4; j++) b2[j] = *(const unsigned long long *)(br + j * 2);
#pragma unroll
            for (int i = 0; i < 8; i++) { float av = ar[i]; a2[i] = pack2(av, av); }
#pragma unroll
            for (int i = 0; i < 8; i++)
#pragma unroll
                for (int j = 0; j < 4; j++) fma2(acc[i][j], a2[i], b2[j]);
        }
    }
#pragma unroll
    for (int i = 0; i < 8; i++) {
        int m = m0 + ty * 8 + i;
#pragma unroll
        for (int j = 0; j < 4; j++) {
            float v0, v1; unpack2(acc[i][j], v0, v1);
            int n = n0 + tx * 8 + j * 2;
            g_xW[(long)m * OUT_D + n] = v0;
            g_xW[(long)m * OUT_D + n + 1] = v1;
        }
    }
}

// ---------------- HMMA bf16 distance sweep + approx top-16 ----------------
// Byte-exact R5/R12 kernel (3786/3818us, tensor 23.5%). FROZEN.
// smem: A 8kblk x 128row x 128B = 131072 | B 2stg x 16KB = 32768 | Ds 128x68 f32 = 34816 | sqj 512
#define SM_A   0
#define SM_B   131072
#define SM_DS  163840
#define SM_SQJ 198656
#define SMEM_KNN 199680
#define DS_STRIDE 68

__global__ void __launch_bounds__(256, 1) knn_hmma_kernel() {
    extern __shared__ char sm[];
    uint32_t sb = smem_u32(sm);
    float *Ds = (float *)(sm + SM_DS);
    float *sqj_s = (float *)(sm + SM_SQJ);

    int tid = threadIdx.x;
    int lane = tid & 31, w = tid >> 5;
    int wm = w >> 2, wn = w & 3;          // warp grid 2(M) x 4(N)
    int hme = wn >> 1;                    // which 64-col half this warp's output is in
    int r0 = blockIdx.x * 128;

    int lrow = lane & 15;
    int lkp  = (lane >> 4) * 8;

    // ---- preload full A tile (8 k-blocks) + B chunk q=0 ----
    {
        const __nv_bfloat16 *Ab = g_hi + (size_t)r0 * DIM;
#pragma unroll
        for (int u = 0; u < 32; u++) {
            int g = tid + u * 256;
            int kblk = g >> 10, rem = g & 1023;
            int row = rem >> 3, k8 = (rem & 7) * 8;
            uint32_t dst = sb + SM_A + kblk * 16384 + SW128(row * 128 + k8 * 2);
            cp_async16(dst, Ab + (size_t)row * DIM + kblk * 64 + k8);
        }
        CP_COMMIT();
#pragma unroll
        for (int u = 0; u < 4; u++) {
            int g = tid + u * 256;
            int row = g >> 3, k8 = (g & 7) * 8;
            uint32_t dst = sb + SM_B + SW128(row * 128 + k8 * 2);
            cp_async16(dst, g_hi + (size_t)row * DIM + k8);   // j=0, kb=0
        }
        CP_COMMIT();
    }

    float bd[NCAND];
    int bi[NCAND];
#pragma unroll
    for (int k = 0; k < NCAND; k++) { bd[k] = INF_F; bi[k] = -1; }
    float th = INF_F;

    for (int j = 0; j < 128; j++) {
        float acc[4][4][4];
#pragma unroll
        for (int a = 0; a < 4; a++)
#pragma unroll
            for (int b = 0; b < 4; b++)
#pragma unroll
                for (int c = 0; c < 4; c++) acc[a][b][c] = 0.f;

        for (int kb = 0; kb < 8; kb++) {
            int q = j * 8 + kb;
            int stage = q & 1;

            // complete chunk q, barrier, THEN overwrite the other stage.
            CP_WAIT(0);
            __syncthreads();
            if (kb == 0 && tid < 128) sqj_s[tid] = g_sq[j * 128 + tid];

            if (q + 1 < 1024) {
                int qn = q + 1;
                int jn = qn >> 3, kbn = qn & 7, sn = stage ^ 1;
#pragma unroll
                for (int u = 0; u < 4; u++) {
                    int g = tid + u * 256;
                    int row = g >> 3, k8 = (g & 7) * 8;
                    uint32_t dst = sb + SM_B + sn * 16384 + SW128(row * 128 + k8 * 2);
                    cp_async16(dst, g_hi + (size_t)(jn * 128 + row) * DIM + kbn * 64 + k8);
                }
                CP_COMMIT();
            }

            uint32_t Ab = sb + SM_A + kb * 16384;
            uint32_t Bb = sb + SM_B + stage * 16384;
#pragma unroll
            for (int ks = 0; ks < 4; ks++) {
                int koff = ks * 16 + lkp;
                uint32_t b0, b1, b2, b3, b4, b5, b6, b7;
                {
                    int n = wn * 32 + lrow;
                    ldsm4(b0, b1, b2, b3, Bb + SW128(n * 128 + koff * 2));
                    ldsm4(b4, b5, b6, b7, Bb + SW128((n + 16) * 128 + koff * 2));
                }
#pragma unroll
                for (int mb = 0; mb < 4; mb++) {
                    uint32_t a0, a1, a2, a3;
                    int m = wm * 64 + mb * 16 + lrow;
                    ldsm4(a0, a1, a2, a3, Ab + SW128(m * 128 + koff * 2));
                    mma_bf16(acc[mb][0][0], acc[mb][0][1], acc[mb][0][2], acc[mb][0][3],
                             a0, a1, a2, a3, b0, b2);
                    mma_bf16(acc[mb][1][0], acc[mb][1][1], acc[mb][1][2], acc[mb][1][3],
                             a0, a1, a2, a3, b1, b3);
                    mma_bf16(acc[mb][2][0], acc[mb][2][1], acc[mb][2][2], acc[mb][2][3],
                             a0, a1, a2, a3, b4, b6);
                    mma_bf16(acc[mb][3][0], acc[mb][3][1], acc[mb][3][2], acc[mb][3][3],
                             a0, a1, a2, a3, b5, b7);
                }
            }
        }

        // ---- epilogue: two 64-col halves through Ds ----
#pragma unroll
        for (int half = 0; half < 2; half++) {
            __syncthreads();
            if (hme == half) {
#pragma unroll
                for (int mb = 0; mb < 4; mb++) {
                    int r1 = wm * 64 + mb * 16 + (lane >> 2);
#pragma unroll
                    for (int nb = 0; nb < 4; nb++) {
                        int cb = (wn & 1) * 32 + nb * 8 + (lane & 3) * 2;
                        float2 v0, v1;
                        v0.x = acc[mb][nb][0]; v0.y = acc[mb][nb][1];
                        v1.x = acc[mb][nb][2]; v1.y = acc[mb][nb][3];
                        *(float2 *)(Ds + r1 * DS_STRIDE + cb) = v0;
                        *(float2 *)(Ds + (r1 + 8) * DS_STRIDE + cb) = v1;
                    }
                }
            }
            __syncthreads();
            {
                int row = tid & 127, seg = tid >> 7;
                int gm = r0 + row;
                const float *dr = Ds + row * DS_STRIDE + seg * 32;
                int ctile = half * 64 + seg * 32;
                int jb = j * 128 + ctile;
#pragma unroll 4
                for (int c4 = 0; c4 < 8; c4++) {
                    float4 v = *(const float4 *)(dr + c4 * 4);
                    const float *sq4 = sqj_s + ctile + c4 * 4;
                    int cb = jb + c4 * 4;
                    float s0 = sq4[0] - 2.0f * v.x;
                    float s1 = sq4[1] - 2.0f * v.y;
                    float s2 = sq4[2] - 2.0f * v.z;
                    float s3 = sq4[3] - 2.0f * v.w;
                    if (s0 < th && cb + 0 != gm) {
                        int p = NCAND - 1;
                        while (p > 0 && bd[p - 1] > s0) { bd[p] = bd[p - 1]; bi[p] = bi[p - 1]; p--; }
                        bd[p] = s0; bi[p] = cb + 0; th = bd[NCAND - 1];
                    }
                    if (s1 < th && cb + 1 != gm) {
                        int p = NCAND - 1;
                        while (p > 0 && bd[p - 1] > s1) { bd[p] = bd[p - 1]; bi[p] = bi[p - 1]; p--; }
                        bd[p] = s1; bi[p] = cb + 1; th = bd[NCAND - 1];
                    }
                    if (s2 < th && cb + 2 != gm) {
                        int p = NCAND - 1;
                        while (p > 0 && bd[p - 1] > s2) { bd[p] = bd[p - 1]; bi[p] = bi[p - 1]; p--; }
                        bd[p] = s2; bi[p] = cb + 2; th = bd[NCAND - 1];
                    }
                    if (s3 < th && cb + 3 != gm) {
                        int p = NCAND - 1;
                        while (p > 0 && bd[p - 1] > s3) { bd[p] = bd[p - 1]; bi[p] = bi[p - 1]; p--; }
                        bd[p] = s3; bi[p] = cb + 3; th = bd[NCAND - 1];
                    }
                }
            }
        }
    }

    // ---- merge the two per-row half-lists, emit top-16 candidates ----
    __syncthreads();
    float *md = Ds;                         // 256*16 floats = Ds[0..4096)
    int *mi = (int *)(Ds + 4096);           // 256*16 ints   = Ds[4096..8192)
#pragma unroll
    for (int k = 0; k < NCAND; k++) {
        md[tid * NCAND + k] = bd[k];
        mi[tid * NCAND + k] = bi[k];
    }
    __syncthreads();
    if (tid < 128) {
        const float *da = md + tid * NCAND;
        const int *ia = mi + tid * NCAND;
        const float *db = md + (tid + 128) * NCAND;
        const int *ib = mi + (tid + 128) * NCAND;
        int pa = 0, pb = 0;
#pragma unroll
        for (int k = 0; k < NCAND; k++) {
            float va = da[pa], vb = db[pb];
            bool takeA = (va < vb) || (va == vb && ia[pa] < ib[pb]);
            int sel = takeA ? ia[pa] : ib[pb];
            if (takeA) pa++; else pb++;
            g_cand[(r0 + tid) * NCAND + k] = sel;
        }
    }
}

// ---------------- exact fp32 rescore + gather-sum ----------------
// Dot product: byte-exact R12 ordering (selection is order-sensitive -> FROZEN).
// Gather-sum: float4 vectorized (identical k-order per element -> bitwise same).
__global__ void __launch_bounds__(512) rescore_kernel(const float *__restrict__ x,
                                                      float *__restrict__ out) {
    __shared__ float xr[512];
    __shared__ float cd[NCAND];
    __shared__ int ci[NCAND];
    __shared__ int sel[KNN];
    int row = blockIdx.x;
    int tid = threadIdx.x;
    int w = tid >> 5, lane = tid & 31;
    xr[tid] = x[(long)row * DIM + tid];
    if (tid < NCAND) {
        int c = g_cand[row * NCAND + tid];
        if (c < 0 || c >= N_PTS) c = -1;    // defensive clamp: never deref garbage
        ci[tid] = c;
    }
    __syncthreads();
    {
        int c = ci[w];
        float s = 0.f;
        if (c >= 0) {
            const float *xc = x + (long)c * DIM;
#pragma unroll
            for (int t = 0; t < 16; t++) {
                int e = lane + 32 * t;
                s += xr[e] * xc[e];
            }
        }
#pragma unroll
        for (int o = 16; o; o >>= 1) s += __shfl_xor_sync(0xFFFFFFFFu, s, o);
        if (lane == 0) cd[w] = (c >= 0) ? (g_sq[row] + g_sq[c] - 2.0f * s) : INF_F;
    }
    __syncthreads();
    if (tid == 0) {
        unsigned used = 0;
        for (int k = 0; k < KNN; k++) {
            float best = INF_F; int bidx = 0x7FFFFFFF, bw = 0;
            for (int q = 0; q < NCAND; q++) {
                if (used & (1u << q)) continue;
                float d = cd[q]; int id = ci[q];
                if (d < best || (d == best && id < bidx)) { best = d; bidx = id; bw = q; }
            }
            used |= 1u << bw;
            sel[k] = bidx;
        }
    }
    __syncthreads();
    // gather-sum: 128 threads x float4 (same per-element k-order as scalar version)
    if (tid < 128) {
        float4 s = make_float4(0.f, 0.f, 0.f, 0.f);
#pragma unroll
        for (int k = 0; k < KNN; k++) {
            float4 v = ((const float4 *)(g_xW + (long)sel[k] * OUT_D))[tid];
            s.x += v.x; s.y += v.y; s.z += v.z; s.w += v.w;
        }
        ((float4 *)(out + (long)row * OUT_D))[tid] = s;
    }
}

// ---------------- launcher ----------------
// Fork xw_kernel onto a side stream so it overlaps knn (knn uses only 128 of
// 148 SMs at 1 CTA/SM; xw fills the idle SMs). Dependencies: prep -> knn;
// xw independent; rescore <- {knn, xw}. Standard capture-legal event pattern.
extern "C" void kernel_launch(void *const *d_in, const int *in_sizes, int n_in,
                              void *d_out, int out_size) {
    const float *x = (const float *)d_in[0];
    const float *A = (const float *)d_in[1];
    float *out = (float *)d_out;

    static int inited = 0;
    static cudaStream_t s1;
    static cudaEvent_t evFork, evJoin;
    if (!inited) {
        cudaFuncSetAttribute(knn_hmma_kernel, cudaFuncAttributeMaxDynamicSharedMemorySize,
                             SMEM_KNN);
        cudaStreamCreateWithFlags(&s1, cudaStreamNonBlocking);
        cudaEventCreateWithFlags(&evFork, cudaEventDisableTiming);
        cudaEventCreateWithFlags(&evJoin, cudaEventDisableTiming);
        inited = 1;
    }

    // fork: side stream joins the captured dependency graph
    cudaEventRecord(evFork, 0);
    cudaStreamWaitEvent(s1, evFork, 0);

    xw_kernel<<<dim3(N_PTS / BM, OUT_D / BN), TPB, 0, s1>>>(x, A);
    cudaEventRecord(evJoin, s1);

    prep_kernel<<<N_PTS / 8, 256>>>(x);
    knn_hmma_kernel<<<N_PTS / 128, TPB, SMEM_KNN>>>();

    // join: rescore needs both knn (main stream) and xw (side stream)
    cudaStreamWaitEvent(0, evJoin, 0);
    rescore_kernel<<<N_PTS, 512>>>(x, out);
}

// round 16
// speedup vs baseline: 1.7428x; 1.0121x over previous
#include <cuda_runtime.h>
#include <cuda_bf16.h>
#include <cstdint>

#define N_PTS 16384
#define DIM   512
#define OUT_D 512
#define KNN   10
#define NCAND 16

// fp32 xw tiling
#define BM 128
#define BN 128
#define KCH 32
#define TPB 256
#define LDS_ 132

#define INF_F __int_as_float(0x7f800000)

__device__ float g_sq[N_PTS];
__device__ float g_xW[N_PTS * OUT_D];
__device__ __nv_bfloat16 g_hi[(size_t)N_PTS * DIM];
__device__ int g_cand[N_PTS * NCAND];

// ---------------- helpers ----------------
__device__ __forceinline__ uint32_t smem_u32(const void *p) {
    uint32_t a;
    asm("{ .reg .u64 t; cvta.to.shared.u64 t, %1; cvt.u32.u64 %0, t; }" : "=r"(a) : "l"(p));
    return a;
}
#define SW128(o) ((o) ^ (((o) >> 3) & 0x70))

__device__ __forceinline__ void cp_async16(uint32_t dst, const void *src) {
    asm volatile("cp.async.cg.shared.global [%0], [%1], 16;" :: "r"(dst), "l"(src) : "memory");
}
#define CP_COMMIT() asm volatile("cp.async.commit_group;" ::: "memory")
#define CP_WAIT(n)  asm volatile("cp.async.wait_group %0;" :: "n"(n) : "memory")

__device__ __forceinline__ void ldsm4(uint32_t &r0, uint32_t &r1, uint32_t &r2, uint32_t &r3,
                                      uint32_t addr) {
    asm volatile("ldmatrix.sync.aligned.m8n8.x4.shared.b16 {%0,%1,%2,%3}, [%4];"
                 : "=r"(r0), "=r"(r1), "=r"(r2), "=r"(r3) : "r"(addr));
}
__device__ __forceinline__ void mma_bf16(float &c0, float &c1, float &c2, float &c3,
                                         uint32_t a0, uint32_t a1, uint32_t a2, uint32_t a3,
                                         uint32_t b0, uint32_t b1) {
    asm volatile("mma.sync.aligned.m16n8k16.row.col.f32.bf16.bf16.f32 "
                 "{%0,%1,%2,%3}, {%4,%5,%6,%7}, {%8,%9}, {%0,%1,%2,%3};"
                 : "+f"(c0), "+f"(c1), "+f"(c2), "+f"(c3)
                 : "r"(a0), "r"(a1), "r"(a2), "r"(a3), "r"(b0), "r"(b1));
}

// ---------------- fused split + row squared norms ----------------
__global__ void __launch_bounds__(256) prep_kernel(const float *__restrict__ x) {
    int row = blockIdx.x * 8 + (threadIdx.x >> 5);
    int lane = threadIdx.x & 31;
    const float4 *xr = (const float4 *)(x + (long)row * DIM);
    uint2 *hr = (uint2 *)(g_hi + (size_t)row * DIM);
    float s = 0.f;
#pragma unroll
    for (int i = 0; i < 4; i++) {
        int idx = lane + i * 32;
        float4 v = xr[idx];
        s += v.x * v.x + v.y * v.y + v.z * v.z + v.w * v.w;
        __nv_bfloat162 p0, p1;
        p0.x = __float2bfloat16_rn(v.x); p0.y = __float2bfloat16_rn(v.y);
        p1.x = __float2bfloat16_rn(v.z); p1.y = __float2bfloat16_rn(v.w);
        uint2 pk;
        pk.x = *(uint32_t *)&p0;
        pk.y = *(uint32_t *)&p1;
        hr[idx] = pk;
    }
#pragma unroll
    for (int o = 16; o; o >>= 1) s += __shfl_xor_sync(0xFFFFFFFFu, s, o);
    if (lane == 0) g_sq[row] = s;
}

// ---------------- fp32 xW = x @ A ----------------
__device__ __forceinline__ unsigned long long pack2(float x, float y) {
    unsigned long long r; asm("mov.b64 %0, {%1, %2};" : "=l"(r) : "f"(x), "f"(y)); return r;
}
__device__ __forceinline__ void unpack2(unsigned long long v, float &a, float &b) {
    asm("mov.b64 {%0, %1}, %2;" : "=f"(a), "=f"(b) : "l"(v));
}
__device__ __forceinline__ void fma2(unsigned long long &d, unsigned long long a, unsigned long long b) {
    asm("fma.rn.f32x2 %0, %1, %2, %0;" : "+l"(d) : "l"(a), "l"(b));
}
__device__ __forceinline__ void load_T(float *dst, const float *__restrict__ src, int row0, int kc, int ld) {
    int t = threadIdx.x;
#pragma unroll
    for (int i = 0; i < 4; i++) {
        int idx = t + i * TPB, r = idx >> 3, f4 = idx & 7;
        float4 v = *(const float4 *)(src + (long)(row0 + r) * ld + kc + f4 * 4);
        dst[(f4 * 4 + 0) * LDS_ + r] = v.x; dst[(f4 * 4 + 1) * LDS_ + r] = v.y;
        dst[(f4 * 4 + 2) * LDS_ + r] = v.z; dst[(f4 * 4 + 3) * LDS_ + r] = v.w;
    }
}
__device__ __forceinline__ void load_N(float *dst, const float *__restrict__ src, int kc, int col0, int ld) {
    int t = threadIdx.x;
#pragma unroll
    for (int i = 0; i < 4; i++) {
        int idx = t + i * TPB, kk = idx >> 5, c4 = idx & 31;
        float4 v = *(const float4 *)(src + (long)(kc + kk) * ld + col0 + c4 * 4);
        *(float4 *)(dst + kk * LDS_ + c4 * 4) = v;
    }
}
__global__ void __launch_bounds__(TPB) xw_kernel(const float *__restrict__ x, const float *__restrict__ A) {
    __shared__ float Xs[KCH * LDS_], Ws[KCH * LDS_];
    int m0 = blockIdx.x * BM, n0 = blockIdx.y * BN;
    int w = threadIdx.x >> 5, l = threadIdx.x & 31;
    int tx = (l & 7) | ((w & 1) << 3), ty = (l >> 3) | ((w >> 1) << 2);
    unsigned long long acc[8][4];
#pragma unroll
    for (int i = 0; i < 8; i++)
#pragma unroll
        for (int j = 0; j < 4; j++) acc[i][j] = 0ull;
    for (int kc = 0; kc < DIM; kc += KCH) {
        __syncthreads();
        load_T(Xs, x, m0, kc, DIM);
        load_N(Ws, A, kc, n0, OUT_D);
        __syncthreads();
#pragma unroll 8
        for (int kk = 0; kk < KCH; kk++) {
            const float *ar = Xs + kk * LDS_ + ty * 8;
            const float *br = Ws + kk * LDS_ + tx * 8;
            unsigned long long b2[4], a2[8];
#pragma unroll
            for (int j = 0; j < 4; j++) b2[j] = *(const unsigned long long *)(br + j * 2);
#pragma unroll
            for (int i = 0; i < 8; i++) { float av = ar[i]; a2[i] = pack2(av, av); }
#pragma unroll
            for (int i = 0; i < 8; i++)
#pragma unroll
                for (int j = 0; j < 4; j++) fma2(acc[i][j], a2[i], b2[j]);
        }
    }
#pragma unroll
    for (int i = 0; i < 8; i++) {
        int m = m0 + ty * 8 + i;
#pragma unroll
        for (int j = 0; j < 4; j++) {
            float v0, v1; unpack2(acc[i][j], v0, v1);
            int n = n0 + tx * 8 + j * 2;
            g_xW[(long)m * OUT_D + n] = v0;
            g_xW[(long)m * OUT_D + n + 1] = v1;
        }
    }
}

// ---------------- HMMA bf16 distance sweep + approx top-16 ----------------
// Byte-exact R5/R12 kernel (3786/3818us, tensor 23.5%). FROZEN.
// smem: A 8kblk x 128row x 128B = 131072 | B 2stg x 16KB = 32768 | Ds 128x68 f32 = 34816 | sqj 512
#define SM_A   0
#define SM_B   131072
#define SM_DS  163840
#define SM_SQJ 198656
#define SMEM_KNN 199680
#define DS_STRIDE 68

__global__ void __launch_bounds__(256, 1) knn_hmma_kernel() {
    extern __shared__ char sm[];
    uint32_t sb = smem_u32(sm);
    float *Ds = (float *)(sm + SM_DS);
    float *sqj_s = (float *)(sm + SM_SQJ);

    int tid = threadIdx.x;
    int lane = tid & 31, w = tid >> 5;
    int wm = w >> 2, wn = w & 3;          // warp grid 2(M) x 4(N)
    int hme = wn >> 1;                    // which 64-col half this warp's output is in
    int r0 = blockIdx.x * 128;

    int lrow = lane & 15;
    int lkp  = (lane >> 4) * 8;

    // ---- preload full A tile (8 k-blocks) + B chunk q=0 ----
    {
        const __nv_bfloat16 *Ab = g_hi + (size_t)r0 * DIM;
#pragma unroll
        for (int u = 0; u < 32; u++) {
            int g = tid + u * 256;
            int kblk = g >> 10, rem = g & 1023;
            int row = rem >> 3, k8 = (rem & 7) * 8;
            uint32_t dst = sb + SM_A + kblk * 16384 + SW128(row * 128 + k8 * 2);
            cp_async16(dst, Ab + (size_t)row * DIM + kblk * 64 + k8);
        }
        CP_COMMIT();
#pragma unroll
        for (int u = 0; u < 4; u++) {
            int g = tid + u * 256;
            int row = g >> 3, k8 = (g & 7) * 8;
            uint32_t dst = sb + SM_B + SW128(row * 128 + k8 * 2);
            cp_async16(dst, g_hi + (size_t)row * DIM + k8);   // j=0, kb=0
        }
        CP_COMMIT();
    }

    float bd[NCAND];
    int bi[NCAND];
#pragma unroll
    for (int k = 0; k < NCAND; k++) { bd[k] = INF_F; bi[k] = -1; }
    float th = INF_F;

    for (int j = 0; j < 128; j++) {
        float acc[4][4][4];
#pragma unroll
        for (int a = 0; a < 4; a++)
#pragma unroll
            for (int b = 0; b < 4; b++)
#pragma unroll
                for (int c = 0; c < 4; c++) acc[a][b][c] = 0.f;

        for (int kb = 0; kb < 8; kb++) {
            int q = j * 8 + kb;
            int stage = q & 1;

            // complete chunk q, barrier, THEN overwrite the other stage.
            CP_WAIT(0);
            __syncthreads();
            if (kb == 0 && tid < 128) sqj_s[tid] = g_sq[j * 128 + tid];

            if (q + 1 < 1024) {
                int qn = q + 1;
                int jn = qn >> 3, kbn = qn & 7, sn = stage ^ 1;
#pragma unroll
                for (int u = 0; u < 4; u++) {
                    int g = tid + u * 256;
                    int row = g >> 3, k8 = (g & 7) * 8;
                    uint32_t dst = sb + SM_B + sn * 16384 + SW128(row * 128 + k8 * 2);
                    cp_async16(dst, g_hi + (size_t)(jn * 128 + row) * DIM + kbn * 64 + k8);
                }
                CP_COMMIT();
            }

            uint32_t Ab = sb + SM_A + kb * 16384;
            uint32_t Bb = sb + SM_B + stage * 16384;
#pragma unroll
            for (int ks = 0; ks < 4; ks++) {
                int koff = ks * 16 + lkp;
                uint32_t b0, b1, b2, b3, b4, b5, b6, b7;
                {
                    int n = wn * 32 + lrow;
                    ldsm4(b0, b1, b2, b3, Bb + SW128(n * 128 + koff * 2));
                    ldsm4(b4, b5, b6, b7, Bb + SW128((n + 16) * 128 + koff * 2));
                }
#pragma unroll
                for (int mb = 0; mb < 4; mb++) {
                    uint32_t a0, a1, a2, a3;
                    int m = wm * 64 + mb * 16 + lrow;
                    ldsm4(a0, a1, a2, a3, Ab + SW128(m * 128 + koff * 2));
                    mma_bf16(acc[mb][0][0], acc[mb][0][1], acc[mb][0][2], acc[mb][0][3],
                             a0, a1, a2, a3, b0, b2);
                    mma_bf16(acc[mb][1][0], acc[mb][1][1], acc[mb][1][2], acc[mb][1][3],
                             a0, a1, a2, a3, b1, b3);
                    mma_bf16(acc[mb][2][0], acc[mb][2][1], acc[mb][2][2], acc[mb][2][3],
                             a0, a1, a2, a3, b4, b6);
                    mma_bf16(acc[mb][3][0], acc[mb][3][1], acc[mb][3][2], acc[mb][3][3],
                             a0, a1, a2, a3, b5, b7);
                }
            }
        }

        // ---- epilogue: two 64-col halves through Ds ----
#pragma unroll
        for (int half = 0; half < 2; half++) {
            __syncthreads();
            if (hme == half) {
#pragma unroll
                for (int mb = 0; mb < 4; mb++) {
                    int r1 = wm * 64 + mb * 16 + (lane >> 2);
#pragma unroll
                    for (int nb = 0; nb < 4; nb++) {
                        int cb = (wn & 1) * 32 + nb * 8 + (lane & 3) * 2;
                        float2 v0, v1;
                        v0.x = acc[mb][nb][0]; v0.y = acc[mb][nb][1];
                        v1.x = acc[mb][nb][2]; v1.y = acc[mb][nb][3];
                        *(float2 *)(Ds + r1 * DS_STRIDE + cb) = v0;
                        *(float2 *)(Ds + (r1 + 8) * DS_STRIDE + cb) = v1;
                    }
                }
            }
            __syncthreads();
            {
                int row = tid & 127, seg = tid >> 7;
                int gm = r0 + row;
                const float *dr = Ds + row * DS_STRIDE + seg * 32;
                int ctile = half * 64 + seg * 32;
                int jb = j * 128 + ctile;
#pragma unroll 4
                for (int c4 = 0; c4 < 8; c4++) {
                    float4 v = *(const float4 *)(dr + c4 * 4);
                    const float *sq4 = sqj_s + ctile + c4 * 4;
                    int cb = jb + c4 * 4;
                    float s0 = sq4[0] - 2.0f * v.x;
                    float s1 = sq4[1] - 2.0f * v.y;
                    float s2 = sq4[2] - 2.0f * v.z;
                    float s3 = sq4[3] - 2.0f * v.w;
                    if (s0 < th && cb + 0 != gm) {
                        int p = NCAND - 1;
                        while (p > 0 && bd[p - 1] > s0) { bd[p] = bd[p - 1]; bi[p] = bi[p - 1]; p--; }
                        bd[p] = s0; bi[p] = cb + 0; th = bd[NCAND - 1];
                    }
                    if (s1 < th && cb + 1 != gm) {
                        int p = NCAND - 1;
                        while (p > 0 && bd[p - 1] > s1) { bd[p] = bd[p - 1]; bi[p] = bi[p - 1]; p--; }
                        bd[p] = s1; bi[p] = cb + 1; th = bd[NCAND - 1];
                    }
                    if (s2 < th && cb + 2 != gm) {
                        int p = NCAND - 1;
                        while (p > 0 && bd[p - 1] > s2) { bd[p] = bd[p - 1]; bi[p] = bi[p - 1]; p--; }
                        bd[p] = s2; bi[p] = cb + 2; th = bd[NCAND - 1];
                    }
                    if (s3 < th && cb + 3 != gm) {
                        int p = NCAND - 1;
                        while (p > 0 && bd[p - 1] > s3) { bd[p] = bd[p - 1]; bi[p] = bi[p - 1]; p--; }
                        bd[p] = s3; bi[p] = cb + 3; th = bd[NCAND - 1];
                    }
                }
            }
        }
    }

    // ---- merge the two per-row half-lists, emit top-16 candidates ----
    __syncthreads();
    float *md = Ds;                         // 256*16 floats = Ds[0..4096)
    int *mi = (int *)(Ds + 4096);           // 256*16 ints   = Ds[4096..8192)
#pragma unroll
    for (int k = 0; k < NCAND; k++) {
        md[tid * NCAND + k] = bd[k];
        mi[tid * NCAND + k] = bi[k];
    }
    __syncthreads();
    if (tid < 128) {
        const float *da = md + tid * NCAND;
        const int *ia = mi + tid * NCAND;
        const float *db = md + (tid + 128) * NCAND;
        const int *ib = mi + (tid + 128) * NCAND;
        int pa = 0, pb = 0;
#pragma unroll
        for (int k = 0; k < NCAND; k++) {
            float va = da[pa], vb = db[pb];
            bool takeA = (va < vb) || (va == vb && ia[pa] < ib[pb]);
            int sel = takeA ? ia[pa] : ib[pb];
            if (takeA) pa++; else pb++;
            g_cand[(r0 + tid) * NCAND + k] = sel;
        }
    }
}

// ---------------- exact fp32 rescore + gather-sum (4 rows per block) ----------------
// Per-candidate dot: byte-exact frozen scalar ordering. Per-row serial selection
// unchanged. Warp w handles candidate w of rows rg..rg+3 sequentially.
#define RROWS 4
__global__ void __launch_bounds__(512) rescore_kernel(const float *__restrict__ x,
                                                      float *__restrict__ out) {
    __shared__ float xr[RROWS][512];
    __shared__ float cd[RROWS][NCAND];
    __shared__ int ci[RROWS][NCAND];
    __shared__ int sel[RROWS][KNN];
    int rg = blockIdx.x * RROWS;
    int tid = threadIdx.x;
    int w = tid >> 5, lane = tid & 31;

    // load 4 rows of x (any pattern; values only)
    {
        int r = tid >> 7, c4 = tid & 127;
        ((float4 *)xr[r])[c4] = ((const float4 *)(x + (long)(rg + r) * DIM))[c4];
    }
    if (tid < RROWS * NCAND) {
        int r = tid / NCAND, q = tid % NCAND;
        int c = g_cand[(rg + r) * NCAND + q];
        if (c < 0 || c >= N_PTS) c = -1;    // defensive clamp
        ci[r][q] = c;
    }
    __syncthreads();

    // warp w: candidate w of each row, frozen scalar dot order per candidate
#pragma unroll
    for (int r = 0; r < RROWS; r++) {
        int c = ci[r][w];
        float s = 0.f;
        if (c >= 0) {
            const float *xc = x + (long)c * DIM;
#pragma unroll
            for (int t = 0; t < 16; t++) {
                int e = lane + 32 * t;
                s += xr[r][e] * xc[e];
            }
        }
#pragma unroll
        for (int o = 16; o; o >>= 1) s += __shfl_xor_sync(0xFFFFFFFFu, s, o);
        if (lane == 0) cd[r][w] = (c >= 0) ? (g_sq[rg + r] + g_sq[c] - 2.0f * s) : INF_F;
    }
    __syncthreads();

    // serial selection, one thread per row (frozen algorithm)
    if (tid < RROWS) {
        int r = tid;
        unsigned used = 0;
        for (int k = 0; k < KNN; k++) {
            float best = INF_F; int bidx = 0x7FFFFFFF, bw = 0;
            for (int q = 0; q < NCAND; q++) {
                if (used & (1u << q)) continue;
                float d = cd[r][q]; int id = ci[r][q];
                if (d < best || (d == best && id < bidx)) { best = d; bidx = id; bw = q; }
            }
            used |= 1u << bw;
            sel[r][k] = bidx;
        }
    }
    __syncthreads();

    // gather-sum: thread -> (row = tid>>7, float4 col = tid&127), frozen k-order
    {
        int r = tid >> 7, c4 = tid & 127;
        float4 s = make_float4(0.f, 0.f, 0.f, 0.f);
#pragma unroll
        for (int k = 0; k < KNN; k++) {
            float4 v = ((const float4 *)(g_xW + (long)sel[r][k] * OUT_D))[c4];
            s.x += v.x; s.y += v.y; s.z += v.z; s.w += v.w;
        }
        ((float4 *)(out + (long)(rg + r) * OUT_D))[c4] = s;
    }
}

// ---------------- launcher ----------------
// xw on a side stream overlaps knn (knn leaves 20 SMs idle). prep -> knn on
// main stream; rescore joins both.
extern "C" void kernel_launch(void *const *d_in, const int *in_sizes, int n_in,
                              void *d_out, int out_size) {
    const float *x = (const float *)d_in[0];
    const float *A = (const float *)d_in[1];
    float *out = (float *)d_out;

    static int inited = 0;
    static cudaStream_t s1;
    static cudaEvent_t evFork, evJoin;
    if (!inited) {
        cudaFuncSetAttribute(knn_hmma_kernel, cudaFuncAttributeMaxDynamicSharedMemorySize,
                             SMEM_KNN);
        cudaStreamCreateWithFlags(&s1, cudaStreamNonBlocking);
        cudaEventCreateWithFlags(&evFork, cudaEventDisableTiming);
        cudaEventCreateWithFlags(&evJoin, cudaEventDisableTiming);
        inited = 1;
    }

    cudaEventRecord(evFork, 0);
    cudaStreamWaitEvent(s1, evFork, 0);

    xw_kernel<<<dim3(N_PTS / BM, OUT_D / BN), TPB, 0, s1>>>(x, A);
    cudaEventRecord(evJoin, s1);

    prep_kernel<<<N_PTS / 8, 256>>>(x);
    knn_hmma_kernel<<<N_PTS / 128, TPB, SMEM_KNN>>>();

    cudaStreamWaitEvent(0, evJoin, 0);
    rescore_kernel<<<N_PTS / RROWS, 512>>>(x, out);
}

// round 17
// speedup vs baseline: 1.7470x; 1.0024x over previous
#include <cuda_runtime.h>
#include <cuda_bf16.h>
#include <cstdint>

#define N_PTS 16384
#define DIM   512
#define OUT_D 512
#define KNN   10
#define NCAND 16

// fp32 xw tiling
#define BM 128
#define BN 128
#define KCH 32
#define TPB 256
#define LDS_ 132

#define INF_F __int_as_float(0x7f800000)

__device__ float g_sq[N_PTS];
__device__ float g_xW[N_PTS * OUT_D];
__device__ __nv_bfloat16 g_hi[(size_t)N_PTS * DIM];
__device__ int g_cand[N_PTS * NCAND];

// ---------------- helpers ----------------
__device__ __forceinline__ uint32_t smem_u32(const void *p) {
    uint32_t a;
    asm("{ .reg .u64 t; cvta.to.shared.u64 t, %1; cvt.u32.u64 %0, t; }" : "=r"(a) : "l"(p));
    return a;
}
#define SW128(o) ((o) ^ (((o) >> 3) & 0x70))

__device__ __forceinline__ void cp_async16(uint32_t dst, const void *src) {
    asm volatile("cp.async.cg.shared.global [%0], [%1], 16;" :: "r"(dst), "l"(src) : "memory");
}
#define CP_COMMIT() asm volatile("cp.async.commit_group;" ::: "memory")
#define CP_WAIT(n)  asm volatile("cp.async.wait_group %0;" :: "n"(n) : "memory")

__device__ __forceinline__ void ldsm4(uint32_t &r0, uint32_t &r1, uint32_t &r2, uint32_t &r3,
                                      uint32_t addr) {
    asm volatile("ldmatrix.sync.aligned.m8n8.x4.shared.b16 {%0,%1,%2,%3}, [%4];"
                 : "=r"(r0), "=r"(r1), "=r"(r2), "=r"(r3) : "r"(addr));
}
__device__ __forceinline__ void mma_bf16(float &c0, float &c1, float &c2, float &c3,
                                         uint32_t a0, uint32_t a1, uint32_t a2, uint32_t a3,
                                         uint32_t b0, uint32_t b1) {
    asm volatile("mma.sync.aligned.m16n8k16.row.col.f32.bf16.bf16.f32 "
                 "{%0,%1,%2,%3}, {%4,%5,%6,%7}, {%8,%9}, {%0,%1,%2,%3};"
                 : "+f"(c0), "+f"(c1), "+f"(c2), "+f"(c3)
                 : "r"(a0), "r"(a1), "r"(a2), "r"(a3), "r"(b0), "r"(b1));
}

// ---------------- fused split + row squared norms ----------------
__global__ void __launch_bounds__(256) prep_kernel(const float *__restrict__ x) {
    int row = blockIdx.x * 8 + (threadIdx.x >> 5);
    int lane = threadIdx.x & 31;
    const float4 *xr = (const float4 *)(x + (long)row * DIM);
    uint2 *hr = (uint2 *)(g_hi + (size_t)row * DIM);
    float s = 0.f;
#pragma unroll
    for (int i = 0; i < 4; i++) {
        int idx = lane + i * 32;
        float4 v = xr[idx];
        s += v.x * v.x + v.y * v.y + v.z * v.z + v.w * v.w;
        __nv_bfloat162 p0, p1;
        p0.x = __float2bfloat16_rn(v.x); p0.y = __float2bfloat16_rn(v.y);
        p1.x = __float2bfloat16_rn(v.z); p1.y = __float2bfloat16_rn(v.w);
        uint2 pk;
        pk.x = *(uint32_t *)&p0;
        pk.y = *(uint32_t *)&p1;
        hr[idx] = pk;
    }
#pragma unroll
    for (int o = 16; o; o >>= 1) s += __shfl_xor_sync(0xFFFFFFFFu, s, o);
    if (lane == 0) g_sq[row] = s;
}

// ---------------- fp32 xW = x @ A ----------------
__device__ __forceinline__ unsigned long long pack2(float x, float y) {
    unsigned long long r; asm("mov.b64 %0, {%1, %2};" : "=l"(r) : "f"(x), "f"(y)); return r;
}
__device__ __forceinline__ void unpack2(unsigned long long v, float &a, float &b) {
    asm("mov.b64 {%0, %1}, %2;" : "=f"(a), "=f"(b) : "l"(v));
}
__device__ __forceinline__ void fma2(unsigned long long &d, unsigned long long a, unsigned long long b) {
    asm("fma.rn.f32x2 %0, %1, %2, %0;" : "+l"(d) : "l"(a), "l"(b));
}
__device__ __forceinline__ void load_T(float *dst, const float *__restrict__ src, int row0, int kc, int ld) {
    int t = threadIdx.x;
#pragma unroll
    for (int i = 0; i < 4; i++) {
        int idx = t + i * TPB, r = idx >> 3, f4 = idx & 7;
        float4 v = *(const float4 *)(src + (long)(row0 + r) * ld + kc + f4 * 4);
        dst[(f4 * 4 + 0) * LDS_ + r] = v.x; dst[(f4 * 4 + 1) * LDS_ + r] = v.y;
        dst[(f4 * 4 + 2) * LDS_ + r] = v.z; dst[(f4 * 4 + 3) * LDS_ + r] = v.w;
    }
}
__device__ __forceinline__ void load_N(float *dst, const float *__restrict__ src, int kc, int col0, int ld) {
    int t = threadIdx.x;
#pragma unroll
    for (int i = 0; i < 4; i++) {
        int idx = t + i * TPB, kk = idx >> 5, c4 = idx & 31;
        float4 v = *(const float4 *)(src + (long)(kc + kk) * ld + col0 + c4 * 4);
        *(float4 *)(dst + kk * LDS_ + c4 * 4) = v;
    }
}
__global__ void __launch_bounds__(TPB) xw_kernel(const float *__restrict__ x, const float *__restrict__ A) {
    __shared__ float Xs[KCH * LDS_], Ws[KCH * LDS_];
    int m0 = blockIdx.x * BM, n0 = blockIdx.y * BN;
    int w = threadIdx.x >> 5, l = threadIdx.x & 31;
    int tx = (l & 7) | ((w & 1) << 3), ty = (l >> 3) | ((w >> 1) << 2);
    unsigned long long acc[8][4];
#pragma unroll
    for (int i = 0; i < 8; i++)
#pragma unroll
        for (int j = 0; j < 4; j++) acc[i][j] = 0ull;
    for (int kc = 0; kc < DIM; kc += KCH) {
        __syncthreads();
        load_T(Xs, x, m0, kc, DIM);
        load_N(Ws, A, kc, n0, OUT_D);
        __syncthreads();
#pragma unroll 8
        for (int kk = 0; kk < KCH; kk++) {
            const float *ar = Xs + kk * LDS_ + ty * 8;
            const float *br = Ws + kk * LDS_ + tx * 8;
            unsigned long long b2[4], a2[8];
#pragma unroll
            for (int j = 0; j < 4; j++) b2[j] = *(const unsigned long long *)(br + j * 2);
#pragma unroll
            for (int i = 0; i < 8; i++) { float av = ar[i]; a2[i] = pack2(av, av); }
#pragma unroll
            for (int i = 0; i < 8; i++)
#pragma unroll
                for (int j = 0; j < 4; j++) fma2(acc[i][j], a2[i], b2[j]);
        }
    }
#pragma unroll
    for (int i = 0; i < 8; i++) {
        int m = m0 + ty * 8 + i;
#pragma unroll
        for (int j = 0; j < 4; j++) {
            float v0, v1; unpack2(acc[i][j], v0, v1);
            int n = n0 + tx * 8 + j * 2;
            g_xW[(long)m * OUT_D + n] = v0;
            g_xW[(long)m * OUT_D + n + 1] = v1;
        }
    }
}

// ---------------- HMMA bf16 distance sweep + approx top-16 ----------------
// Byte-exact R5/R12 kernel (3786/3818us, tensor 23.5%). FROZEN.
// smem: A 8kblk x 128row x 128B = 131072 | B 2stg x 16KB = 32768 | Ds 128x68 f32 = 34816 | sqj 512
#define SM_A   0
#define SM_B   131072
#define SM_DS  163840
#define SM_SQJ 198656
#define SMEM_KNN 199680
#define DS_STRIDE 68

__global__ void __launch_bounds__(256, 1) knn_hmma_kernel() {
    extern __shared__ char sm[];
    uint32_t sb = smem_u32(sm);
    float *Ds = (float *)(sm + SM_DS);
    float *sqj_s = (float *)(sm + SM_SQJ);

    int tid = threadIdx.x;
    int lane = tid & 31, w = tid >> 5;
    int wm = w >> 2, wn = w & 3;          // warp grid 2(M) x 4(N)
    int hme = wn >> 1;                    // which 64-col half this warp's output is in
    int r0 = blockIdx.x * 128;

    int lrow = lane & 15;
    int lkp  = (lane >> 4) * 8;

    // ---- preload full A tile (8 k-blocks) + B chunk q=0 ----
    {
        const __nv_bfloat16 *Ab = g_hi + (size_t)r0 * DIM;
#pragma unroll
        for (int u = 0; u < 32; u++) {
            int g = tid + u * 256;
            int kblk = g >> 10, rem = g & 1023;
            int row = rem >> 3, k8 = (rem & 7) * 8;
            uint32_t dst = sb + SM_A + kblk * 16384 + SW128(row * 128 + k8 * 2);
            cp_async16(dst, Ab + (size_t)row * DIM + kblk * 64 + k8);
        }
        CP_COMMIT();
#pragma unroll
        for (int u = 0; u < 4; u++) {
            int g = tid + u * 256;
            int row = g >> 3, k8 = (g & 7) * 8;
            uint32_t dst = sb + SM_B + SW128(row * 128 + k8 * 2);
            cp_async16(dst, g_hi + (size_t)row * DIM + k8);   // j=0, kb=0
        }
        CP_COMMIT();
    }

    float bd[NCAND];
    int bi[NCAND];
#pragma unroll
    for (int k = 0; k < NCAND; k++) { bd[k] = INF_F; bi[k] = -1; }
    float th = INF_F;

    for (int j = 0; j < 128; j++) {
        float acc[4][4][4];
#pragma unroll
        for (int a = 0; a < 4; a++)
#pragma unroll
            for (int b = 0; b < 4; b++)
#pragma unroll
                for (int c = 0; c < 4; c++) acc[a][b][c] = 0.f;

        for (int kb = 0; kb < 8; kb++) {
            int q = j * 8 + kb;
            int stage = q & 1;

            // complete chunk q, barrier, THEN overwrite the other stage.
            CP_WAIT(0);
            __syncthreads();
            if (kb == 0 && tid < 128) sqj_s[tid] = g_sq[j * 128 + tid];

            if (q + 1 < 1024) {
                int qn = q + 1;
                int jn = qn >> 3, kbn = qn & 7, sn = stage ^ 1;
#pragma unroll
                for (int u = 0; u < 4; u++) {
                    int g = tid + u * 256;
                    int row = g >> 3, k8 = (g & 7) * 8;
                    uint32_t dst = sb + SM_B + sn * 16384 + SW128(row * 128 + k8 * 2);
                    cp_async16(dst, g_hi + (size_t)(jn * 128 + row) * DIM + kbn * 64 + k8);
                }
                CP_COMMIT();
            }

            uint32_t Ab = sb + SM_A + kb * 16384;
            uint32_t Bb = sb + SM_B + stage * 16384;
#pragma unroll
            for (int ks = 0; ks < 4; ks++) {
                int koff = ks * 16 + lkp;
                uint32_t b0, b1, b2, b3, b4, b5, b6, b7;
                {
                    int n = wn * 32 + lrow;
                    ldsm4(b0, b1, b2, b3, Bb + SW128(n * 128 + koff * 2));
                    ldsm4(b4, b5, b6, b7, Bb + SW128((n + 16) * 128 + koff * 2));
                }
#pragma unroll
                for (int mb = 0; mb < 4; mb++) {
                    uint32_t a0, a1, a2, a3;
                    int m = wm * 64 + mb * 16 + lrow;
                    ldsm4(a0, a1, a2, a3, Ab + SW128(m * 128 + koff * 2));
                    mma_bf16(acc[mb][0][0], acc[mb][0][1], acc[mb][0][2], acc[mb][0][3],
                             a0, a1, a2, a3, b0, b2);
                    mma_bf16(acc[mb][1][0], acc[mb][1][1], acc[mb][1][2], acc[mb][1][3],
                             a0, a1, a2, a3, b1, b3);
                    mma_bf16(acc[mb][2][0], acc[mb][2][1], acc[mb][2][2], acc[mb][2][3],
                             a0, a1, a2, a3, b4, b6);
                    mma_bf16(acc[mb][3][0], acc[mb][3][1], acc[mb][3][2], acc[mb][3][3],
                             a0, a1, a2, a3, b5, b7);
                }
            }
        }

        // ---- epilogue: two 64-col halves through Ds ----
#pragma unroll
        for (int half = 0; half < 2; half++) {
            __syncthreads();
            if (hme == half) {
#pragma unroll
                for (int mb = 0; mb < 4; mb++) {
                    int r1 = wm * 64 + mb * 16 + (lane >> 2);
#pragma unroll
                    for (int nb = 0; nb < 4; nb++) {
                        int cb = (wn & 1) * 32 + nb * 8 + (lane & 3) * 2;
                        float2 v0, v1;
                        v0.x = acc[mb][nb][0]; v0.y = acc[mb][nb][1];
                        v1.x = acc[mb][nb][2]; v1.y = acc[mb][nb][3];
                        *(float2 *)(Ds + r1 * DS_STRIDE + cb) = v0;
                        *(float2 *)(Ds + (r1 + 8) * DS_STRIDE + cb) = v1;
                    }
                }
            }
            __syncthreads();
            {
                int row = tid & 127, seg = tid >> 7;
                int gm = r0 + row;
                const float *dr = Ds + row * DS_STRIDE + seg * 32;
                int ctile = half * 64 + seg * 32;
                int jb = j * 128 + ctile;
#pragma unroll 4
                for (int c4 = 0; c4 < 8; c4++) {
                    float4 v = *(const float4 *)(dr + c4 * 4);
                    const float *sq4 = sqj_s + ctile + c4 * 4;
                    int cb = jb + c4 * 4;
                    float s0 = sq4[0] - 2.0f * v.x;
                    float s1 = sq4[1] - 2.0f * v.y;
                    float s2 = sq4[2] - 2.0f * v.z;
                    float s3 = sq4[3] - 2.0f * v.w;
                    if (s0 < th && cb + 0 != gm) {
                        int p = NCAND - 1;
                        while (p > 0 && bd[p - 1] > s0) { bd[p] = bd[p - 1]; bi[p] = bi[p - 1]; p--; }
                        bd[p] = s0; bi[p] = cb + 0; th = bd[NCAND - 1];
                    }
                    if (s1 < th && cb + 1 != gm) {
                        int p = NCAND - 1;
                        while (p > 0 && bd[p - 1] > s1) { bd[p] = bd[p - 1]; bi[p] = bi[p - 1]; p--; }
                        bd[p] = s1; bi[p] = cb + 1; th = bd[NCAND - 1];
                    }
                    if (s2 < th && cb + 2 != gm) {
                        int p = NCAND - 1;
                        while (p > 0 && bd[p - 1] > s2) { bd[p] = bd[p - 1]; bi[p] = bi[p - 1]; p--; }
                        bd[p] = s2; bi[p] = cb + 2; th = bd[NCAND - 1];
                    }
                    if (s3 < th && cb + 3 != gm) {
                        int p = NCAND - 1;
                        while (p > 0 && bd[p - 1] > s3) { bd[p] = bd[p - 1]; bi[p] = bi[p - 1]; p--; }
                        bd[p] = s3; bi[p] = cb + 3; th = bd[NCAND - 1];
                    }
                }
            }
        }
    }

    // ---- merge the two per-row half-lists, emit top-16 candidates ----
    __syncthreads();
    float *md = Ds;                         // 256*16 floats = Ds[0..4096)
    int *mi = (int *)(Ds + 4096);           // 256*16 ints   = Ds[4096..8192)
#pragma unroll
    for (int k = 0; k < NCAND; k++) {
        md[tid * NCAND + k] = bd[k];
        mi[tid * NCAND + k] = bi[k];
    }
    __syncthreads();
    if (tid < 128) {
        const float *da = md + tid * NCAND;
        const int *ia = mi + tid * NCAND;
        const float *db = md + (tid + 128) * NCAND;
        const int *ib = mi + (tid + 128) * NCAND;
        int pa = 0, pb = 0;
#pragma unroll
        for (int k = 0; k < NCAND; k++) {
            float va = da[pa], vb = db[pb];
            bool takeA = (va < vb) || (va == vb && ia[pa] < ib[pb]);
            int sel = takeA ? ia[pa] : ib[pb];
            if (takeA) pa++; else pb++;
            g_cand[(r0 + tid) * NCAND + k] = sel;
        }
    }
}

// ---------------- exact fp32 rescore + gather-sum (8 rows per block) ----------------
// Per-candidate dot: byte-exact frozen scalar ordering. Per-row serial selection
// unchanged. Warp w handles candidate w of rows rg..rg+7 sequentially.
#define RROWS 8
__global__ void __launch_bounds__(512) rescore_kernel(const float *__restrict__ x,
                                                      float *__restrict__ out) {
    __shared__ float xr[RROWS][512];
    __shared__ float cd[RROWS][NCAND];
    __shared__ int ci[RROWS][NCAND];
    __shared__ int sel[RROWS][KNN];
    int rg = blockIdx.x * RROWS;
    int tid = threadIdx.x;
    int w = tid >> 5, lane = tid & 31;

    // load 8 rows of x: thread -> (row = tid>>6, 2 float4 cols)
    {
        int r = tid >> 6, c = tid & 63;
#pragma unroll
        for (int h = 0; h < 2; h++)
            ((float4 *)xr[r])[c + 64 * h] =
                ((const float4 *)(x + (long)(rg + r) * DIM))[c + 64 * h];
    }
    if (tid < RROWS * NCAND) {
        int r = tid / NCAND, q = tid % NCAND;
        int c = g_cand[(rg + r) * NCAND + q];
        if (c < 0 || c >= N_PTS) c = -1;    // defensive clamp
        ci[r][q] = c;
    }
    __syncthreads();

    // warp w: candidate w of each row, frozen scalar dot order per candidate
#pragma unroll
    for (int r = 0; r < RROWS; r++) {
        int c = ci[r][w];
        float s = 0.f;
        if (c >= 0) {
            const float *xc = x + (long)c * DIM;
#pragma unroll
            for (int t = 0; t < 16; t++) {
                int e = lane + 32 * t;
                s += xr[r][e] * xc[e];
            }
        }
#pragma unroll
        for (int o = 16; o; o >>= 1) s += __shfl_xor_sync(0xFFFFFFFFu, s, o);
        if (lane == 0) cd[r][w] = (c >= 0) ? (g_sq[rg + r] + g_sq[c] - 2.0f * s) : INF_F;
    }
    __syncthreads();

    // serial selection, one thread per row (frozen algorithm)
    if (tid < RROWS) {
        int r = tid;
        unsigned used = 0;
        for (int k = 0; k < KNN; k++) {
            float best = INF_F; int bidx = 0x7FFFFFFF, bw = 0;
            for (int q = 0; q < NCAND; q++) {
                if (used & (1u << q)) continue;
                float d = cd[r][q]; int id = ci[r][q];
                if (d < best || (d == best && id < bidx)) { best = d; bidx = id; bw = q; }
            }
            used |= 1u << bw;
            sel[r][k] = bidx;
        }
    }
    __syncthreads();

    // gather-sum: thread -> (row = tid>>6, 2 float4 cols), frozen k-order per element
    {
        int r = tid >> 6, c = tid & 63;
#pragma unroll
        for (int h = 0; h < 2; h++) {
            int c4 = c + 64 * h;
            float4 s = make_float4(0.f, 0.f, 0.f, 0.f);
#pragma unroll
            for (int k = 0; k < KNN; k++) {
                float4 v = ((const float4 *)(g_xW + (long)sel[r][k] * OUT_D))[c4];
                s.x += v.x; s.y += v.y; s.z += v.z; s.w += v.w;
            }
            ((float4 *)(out + (long)(rg + r) * OUT_D))[c4] = s;
        }
    }
}

// ---------------- launcher ----------------
// xw on a side stream overlaps knn (knn leaves 20 SMs idle). prep -> knn on
// main stream; rescore joins both.
extern "C" void kernel_launch(void *const *d_in, const int *in_sizes, int n_in,
                              void *d_out, int out_size) {
    const float *x = (const float *)d_in[0];
    const float *A = (const float *)d_in[1];
    float *out = (float *)d_out;

    static int inited = 0;
    static cudaStream_t s1;
    static cudaEvent_t evFork, evJoin;
    if (!inited) {
        cudaFuncSetAttribute(knn_hmma_kernel, cudaFuncAttributeMaxDynamicSharedMemorySize,
                             SMEM_KNN);
        cudaStreamCreateWithFlags(&s1, cudaStreamNonBlocking);
        cudaEventCreateWithFlags(&evFork, cudaEventDisableTiming);
        cudaEventCreateWithFlags(&evJoin, cudaEventDisableTiming);
        inited = 1;
    }

    cudaEventRecord(evFork, 0);
    cudaStreamWaitEvent(s1, evFork, 0);

    xw_kernel<<<dim3(N_PTS / BM, OUT_D / BN), TPB, 0, s1>>>(x, A);
    cudaEventRecord(evJoin, s1);

    prep_kernel<<<N_PTS / 8, 256>>>(x);
    knn_hmma_kernel<<<N_PTS / 128, TPB, SMEM_KNN>>>();

    cudaStreamWaitEvent(0, evJoin, 0);
    rescore_kernel<<<N_PTS / RROWS, 512>>>(x, out);
}